// round 2
// baseline (speedup 1.0000x reference)
#include <cuda_runtime.h>
#include <cuda_bf16.h>
#include <cstdint>

#define NB 64
#define NN 512
#define KNB 8
#define NODES 32768
#define EDGES 262144
#define CATD 1030

// ---------------- scratch (device globals; no allocation allowed) ----------------
__device__ float g_D[(size_t)NODES * 512];      // distances [B*N, N]
__device__ float g_E[(size_t)EDGES * 512];      // edge features (ld = 2F)
__device__ float g_H1[(size_t)EDGES * 336];     // hidden 1
__device__ float g_H2[(size_t)EDGES * 256];     // hidden 2
__device__ float g_CAT[(size_t)NODES * CATD];   // [x0 | x1 | x2 | x3 | x4]
__device__ float g_X2[NODES];                   // squared norms
__device__ int   g_IDX[NODES * KNB];            // knn indices (within-graph)
__device__ float g_G[64 * 256];                 // pooled
__device__ float g_T[64 * 128];                 // head hidden

__device__ __forceinline__ float lrelu(float v) { return (v >= 0.f) ? v : 0.01f * v; }

// ---------------- squared norms ----------------
__global__ void de_sqnorm(const float* __restrict__ X, int ldx, int F, float* __restrict__ x2) {
    int i = blockIdx.x * blockDim.x + threadIdx.x;
    if (i < NODES) {
        const float* r = X + (size_t)i * ldx;
        float s = 0.f;
        for (int f = 0; f < F; f++) { float v = r[f]; s += v * v; }
        x2[i] = s;
    }
}

// ---------------- pairwise distance tile (per-graph Gram) ----------------
__global__ void de_dist(const float* __restrict__ X, int ldx, int F,
                        const float* __restrict__ x2, float* __restrict__ D) {
    __shared__ float As[16][68];
    __shared__ float Bs[16][68];
    int b  = blockIdx.z;
    const float* Xb = X + (size_t)b * NN * ldx;
    int n0 = blockIdx.y * 64, m0 = blockIdx.x * 64;
    int tx = threadIdx.x & 15, ty = threadIdx.x >> 4;
    float acc[4][4] = {};
    for (int k0 = 0; k0 < F; k0 += 16) {
        for (int i = threadIdx.x; i < 1024; i += 256) {
            int kk = i & 15, rr = i >> 4;
            int k = k0 + kk;
            As[kk][rr] = (k < F) ? Xb[(size_t)(n0 + rr) * ldx + k] : 0.f;
            Bs[kk][rr] = (k < F) ? Xb[(size_t)(m0 + rr) * ldx + k] : 0.f;
        }
        __syncthreads();
#pragma unroll
        for (int kk = 0; kk < 16; kk++) {
            float4 a4 = *(const float4*)&As[kk][ty * 4];
            float4 w4 = *(const float4*)&Bs[kk][tx * 4];
            float av[4] = {a4.x, a4.y, a4.z, a4.w};
            float wv[4] = {w4.x, w4.y, w4.z, w4.w};
#pragma unroll
            for (int i = 0; i < 4; i++)
#pragma unroll
                for (int j = 0; j < 4; j++) acc[i][j] += av[i] * wv[j];
        }
        __syncthreads();
    }
    int nb = b * NN;
#pragma unroll
    for (int i = 0; i < 4; i++) {
        int n = n0 + ty * 4 + i;
        float xn = x2[nb + n];
#pragma unroll
        for (int j = 0; j < 4; j++) {
            int m = m0 + tx * 4 + j;
            D[((size_t)(nb + n)) * NN + m] = xn + x2[nb + m] - 2.f * acc[i][j];
        }
    }
}

// ---------------- top-8 smallest (ties -> lowest index, matches lax.top_k) ----------------
__global__ void de_topk(const float* __restrict__ D, int* __restrict__ idx) {
    __shared__ float sd[NN];
    __shared__ float rv[128];
    __shared__ int   ri[128];
    int row = blockIdx.x;
    int tid = threadIdx.x;
    const float* d = D + (size_t)row * NN;
    for (int m = tid; m < NN; m += 128) sd[m] = d[m];
    __syncthreads();
    for (int t = 0; t < KNB; t++) {
        float bv = 3.4e38f; int bi = NN;
        for (int m = tid; m < NN; m += 128) {
            float v = sd[m];
            if (v < bv || (v == bv && m < bi)) { bv = v; bi = m; }
        }
        rv[tid] = bv; ri[tid] = bi;
        __syncthreads();
        for (int s = 64; s > 0; s >>= 1) {
            if (tid < s) {
                if (rv[tid + s] < rv[tid] || (rv[tid + s] == rv[tid] && ri[tid + s] < ri[tid])) {
                    rv[tid] = rv[tid + s]; ri[tid] = ri[tid + s];
                }
            }
            __syncthreads();
        }
        if (tid == 0) { idx[row * KNB + t] = ri[0]; sd[ri[0]] = 3.4e38f; }
        __syncthreads();
    }
}

// ---------------- edge feature build: e = [xi, xj - xi] ----------------
__global__ void de_edge_build(const float* __restrict__ X, int ldx, int F,
                              const int* __restrict__ idx, float* __restrict__ E, int ldE) {
    __shared__ float sxi[256];
    int node = blockIdx.x;
    int b = node >> 9;  // node / 512
    const float* xi = X + (size_t)node * ldx;
    for (int f = threadIdx.x; f < F; f += blockDim.x) sxi[f] = xi[f];
    __syncthreads();
    for (int k = 0; k < KNB; k++) {
        int m = idx[node * KNB + k];
        const float* xj = X + (size_t)(b * NN + m) * ldx;
        float* e = E + ((size_t)node * KNB + k) * ldE;
        for (int f = threadIdx.x; f < F; f += blockDim.x) {
            float a = sxi[f];
            float bj = xj[f];
            e[f] = a;
            e[F + f] = bj - a;
        }
    }
}

// ---------------- C = lrelu(A@W + bias); A[M,K](lda) W[K,N] row-major, C[M,N](ldc) ----------------
__global__ void de_gemm(const float* __restrict__ A, const float* __restrict__ W,
                        const float* __restrict__ bias, float* __restrict__ C,
                        int M, int Nc, int Kc, int lda, int ldc) {
    __shared__ float As[16][68];
    __shared__ float Ws[16][68];
    int m0 = blockIdx.y * 64;
    int n0 = blockIdx.x * 64;
    int tx = threadIdx.x & 15, ty = threadIdx.x >> 4;
    float acc[4][4] = {};
    for (int k0 = 0; k0 < Kc; k0 += 16) {
        for (int i = threadIdx.x; i < 1024; i += 256) {
            int kk = i & 15, mm = i >> 4;
            int m = m0 + mm, k = k0 + kk;
            As[kk][mm] = (m < M && k < Kc) ? A[(size_t)m * lda + k] : 0.f;
        }
        for (int i = threadIdx.x; i < 1024; i += 256) {
            int nn = i & 63, kk = i >> 6;
            int n = n0 + nn, k = k0 + kk;
            Ws[kk][nn] = (n < Nc && k < Kc) ? W[(size_t)k * Nc + n] : 0.f;
        }
        __syncthreads();
#pragma unroll
        for (int kk = 0; kk < 16; kk++) {
            float4 a4 = *(const float4*)&As[kk][ty * 4];
            float4 w4 = *(const float4*)&Ws[kk][tx * 4];
            float av[4] = {a4.x, a4.y, a4.z, a4.w};
            float wv[4] = {w4.x, w4.y, w4.z, w4.w};
#pragma unroll
            for (int i = 0; i < 4; i++)
#pragma unroll
                for (int j = 0; j < 4; j++) acc[i][j] += av[i] * wv[j];
        }
        __syncthreads();
    }
#pragma unroll
    for (int i = 0; i < 4; i++) {
        int m = m0 + ty * 4 + i;
        if (m >= M) continue;
#pragma unroll
        for (int j = 0; j < 4; j++) {
            int n = n0 + tx * 4 + j;
            if (n >= Nc) continue;
            float v = acc[i][j] + bias[n];
            C[(size_t)m * ldc + n] = lrelu(v);
        }
    }
}

// ---------------- max over K edges per node -> CAT column block ----------------
__global__ void de_maxk(const float* __restrict__ H2, float* __restrict__ CAT, int colOff) {
    int i = blockIdx.x * blockDim.x + threadIdx.x;
    if (i >= NODES * 256) return;
    int node = i >> 8, c = i & 255;
    const float* h = H2 + ((size_t)node * KNB) * 256 + c;
    float m = h[0];
#pragma unroll
    for (int k = 1; k < KNB; k++) m = fmaxf(m, h[(size_t)k * 256]);
    CAT[(size_t)node * CATD + colOff + c] = m;
}

// ---------------- copy x0 into CAT cols 0..5 ----------------
__global__ void de_copyx(const float* __restrict__ x, float* __restrict__ CAT) {
    int i = blockIdx.x * blockDim.x + threadIdx.x;
    if (i >= NODES * 6) return;
    int node = i / 6, f = i % 6;
    CAT[(size_t)node * CATD + f] = x[(size_t)node * 6 + f];
}

// ---------------- mean pool over N per graph ----------------
__global__ void de_mean(const float* __restrict__ H, float* __restrict__ G) {
    int b = blockIdx.x, c = threadIdx.x;
    float s = 0.f;
    for (int n = 0; n < NN; n++) s += H[((size_t)b * NN + n) * 256 + c];
    G[b * 256 + c] = s * (1.f / NN);
}

// ---------------- head ----------------
__global__ void de_head1(const float* __restrict__ G, const float* __restrict__ W,
                         const float* __restrict__ bias, float* __restrict__ T) {
    int b = blockIdx.x, j = threadIdx.x;  // 128 threads
    float s = bias[j];
    for (int c = 0; c < 256; c++) s += G[b * 256 + c] * W[c * 128 + j];
    T[b * 128 + j] = lrelu(s);
}

__global__ void de_head2(const float* __restrict__ T, const float* __restrict__ W,
                         const float* __restrict__ bias, float* __restrict__ out) {
    int b = blockIdx.x, o = threadIdx.x;
    if (o >= 3) return;
    float s = bias[o];
    for (int j = 0; j < 128; j++) s += T[b * 128 + j] * W[j * 3 + o];
    out[b * 3 + o] = s;
}

// ---------------- launch ----------------
extern "C" void kernel_launch(void* const* d_in, const int* in_sizes, int n_in,
                              void* d_out, int out_size) {
    (void)in_sizes; (void)n_in; (void)out_size;
    const float* x = (const float*)d_in[0];
    // d_in[1] edge_index (unused), d_in[2] batch (unused)
    const float* cw1[4], *cb1[4], *cw2[4], *cb2[4];
    for (int l = 0; l < 4; l++) {
        cw1[l] = (const float*)d_in[3 + 4 * l];
        cb1[l] = (const float*)d_in[4 + 4 * l];
        cw2[l] = (const float*)d_in[5 + 4 * l];
        cb2[l] = (const float*)d_in[6 + 4 * l];
    }
    const float* m1w1 = (const float*)d_in[19];
    const float* m1b1 = (const float*)d_in[20];
    const float* m1w2 = (const float*)d_in[21];
    const float* m1b2 = (const float*)d_in[22];
    const float* m2w1 = (const float*)d_in[23];
    const float* m2b1 = (const float*)d_in[24];
    const float* m2w2 = (const float*)d_in[25];
    const float* m2b2 = (const float*)d_in[26];

    float *D, *E, *H1, *H2, *CAT, *X2, *G, *T;
    int* IDX;
    cudaGetSymbolAddress((void**)&D,   g_D);
    cudaGetSymbolAddress((void**)&E,   g_E);
    cudaGetSymbolAddress((void**)&H1,  g_H1);
    cudaGetSymbolAddress((void**)&H2,  g_H2);
    cudaGetSymbolAddress((void**)&CAT, g_CAT);
    cudaGetSymbolAddress((void**)&X2,  g_X2);
    cudaGetSymbolAddress((void**)&IDX, g_IDX);
    cudaGetSymbolAddress((void**)&G,   g_G);
    cudaGetSymbolAddress((void**)&T,   g_T);

    de_copyx<<<(NODES * 6 + 255) / 256, 256>>>(x, CAT);

    for (int l = 0; l < 4; l++) {
        const float* Xsrc;
        int ldx, F, off;
        if (l == 0) { Xsrc = x; ldx = 6; F = 6; off = 6; }
        else        { Xsrc = CAT + (6 + (l - 1) * 256); ldx = CATD; F = 256; off = 6 + l * 256; }
        int twoF = 2 * F;

        de_sqnorm<<<(NODES + 255) / 256, 256>>>(Xsrc, ldx, F, X2);
        de_dist<<<dim3(8, 8, NB), 256>>>(Xsrc, ldx, F, X2, D);
        de_topk<<<NODES, 128>>>(D, IDX);
        de_edge_build<<<NODES, 256>>>(Xsrc, ldx, F, IDX, E, twoF);
        de_gemm<<<dim3(6, EDGES / 64), 256>>>(E, cw1[l], cb1[l], H1, EDGES, 336, twoF, twoF, 336);
        de_gemm<<<dim3(4, EDGES / 64), 256>>>(H1, cw2[l], cb2[l], H2, EDGES, 256, 336, 336, 256);
        de_maxk<<<(NODES * 256 + 255) / 256, 256>>>(H2, CAT, off);
    }

    // mlp1: [NODES,1030] -> 336 -> 256 (lrelu after both)
    de_gemm<<<dim3(6, NODES / 64), 256>>>(CAT, m1w1, m1b1, H1, NODES, 336, CATD, CATD, 336);
    de_gemm<<<dim3(4, NODES / 64), 256>>>(H1, m1w2, m1b2, H2, NODES, 256, 336, 336, 256);

    de_mean<<<NB, 256>>>(H2, G);
    de_head1<<<NB, 128>>>(G, m2w1, m2b1, T);
    de_head2<<<NB, 32>>>(T, m2w2, m2b2, (float*)d_out);
}

// round 3
// speedup vs baseline: 1.9499x; 1.9499x over previous
#include <cuda_runtime.h>
#include <cuda_bf16.h>
#include <mma.h>
#include <cstdint>

using namespace nvcuda;

#define NB 64
#define NN 512
#define KNB 8
#define NODES 32768
#define EDGES 262144
#define CATD 1030
#define CATP 1056   // CATD padded to mult of 32
#define H1P  352    // 336 padded to mult of 32

// ---------------- scratch (device globals; no runtime allocation) ----------------
__device__ float g_D[(size_t)NODES * 512];           // distances
__device__ __nv_bfloat16 g_Eh[(size_t)EDGES * 512];  // edge features hi (lda = Kpad)
__device__ __nv_bfloat16 g_El[(size_t)EDGES * 512];  // edge features lo
__device__ __nv_bfloat16 g_H1h[(size_t)EDGES * H1P]; // hidden1 hi (lda = 352)
__device__ __nv_bfloat16 g_H1l[(size_t)EDGES * H1P]; // hidden1 lo
__device__ float g_H2[(size_t)EDGES * 256];          // hidden2 fp32
__device__ float g_CAT[(size_t)NODES * CATD];        // concat features fp32
__device__ __nv_bfloat16 g_CATh[(size_t)NODES * CATP];
__device__ __nv_bfloat16 g_CATl[(size_t)NODES * CATP];
__device__ float g_X2[NODES];
__device__ int   g_IDX[NODES * KNB];
__device__ float g_G[64 * 256];
__device__ float g_T[64 * 128];
__device__ __nv_bfloat16 g_W1h[1030 * 336];
__device__ __nv_bfloat16 g_W1l[1030 * 336];
__device__ __nv_bfloat16 g_W2h[336 * 256];
__device__ __nv_bfloat16 g_W2l[336 * 256];

__device__ __forceinline__ float lrelu(float v) { return (v >= 0.f) ? v : 0.01f * v; }

// ---------------- squared norms ----------------
__global__ void de_sqnorm(const float* __restrict__ X, int ldx, int F, float* __restrict__ x2) {
    int i = blockIdx.x * blockDim.x + threadIdx.x;
    if (i < NODES) {
        const float* r = X + (size_t)i * ldx;
        float s = 0.f;
        for (int f = 0; f < F; f++) { float v = r[f]; s += v * v; }
        x2[i] = s;
    }
}

// ---------------- pairwise distance (fp32, bit-stable kNN) ----------------
__global__ void de_dist(const float* __restrict__ X, int ldx, int F,
                        const float* __restrict__ x2, float* __restrict__ D) {
    __shared__ float As[16][68];
    __shared__ float Bs[16][68];
    int b  = blockIdx.z;
    const float* Xb = X + (size_t)b * NN * ldx;
    int n0 = blockIdx.y * 64, m0 = blockIdx.x * 64;
    int tx = threadIdx.x & 15, ty = threadIdx.x >> 4;
    float acc[4][4] = {};
    for (int k0 = 0; k0 < F; k0 += 16) {
        for (int i = threadIdx.x; i < 1024; i += 256) {
            int kk = i & 15, rr = i >> 4;
            int k = k0 + kk;
            As[kk][rr] = (k < F) ? Xb[(size_t)(n0 + rr) * ldx + k] : 0.f;
            Bs[kk][rr] = (k < F) ? Xb[(size_t)(m0 + rr) * ldx + k] : 0.f;
        }
        __syncthreads();
#pragma unroll
        for (int kk = 0; kk < 16; kk++) {
            float4 a4 = *(const float4*)&As[kk][ty * 4];
            float4 w4 = *(const float4*)&Bs[kk][tx * 4];
            float av[4] = {a4.x, a4.y, a4.z, a4.w};
            float wv[4] = {w4.x, w4.y, w4.z, w4.w};
#pragma unroll
            for (int i = 0; i < 4; i++)
#pragma unroll
                for (int j = 0; j < 4; j++) acc[i][j] += av[i] * wv[j];
        }
        __syncthreads();
    }
    int nb = b * NN;
#pragma unroll
    for (int i = 0; i < 4; i++) {
        int n = n0 + ty * 4 + i;
        float xn = x2[nb + n];
#pragma unroll
        for (int j = 0; j < 4; j++) {
            int m = m0 + tx * 4 + j;
            D[((size_t)(nb + n)) * NN + m] = xn + x2[nb + m] - 2.f * acc[i][j];
        }
    }
}

// ---------------- top-8 smallest ----------------
__global__ void de_topk(const float* __restrict__ D, int* __restrict__ idx) {
    __shared__ float sd[NN];
    __shared__ float rv[128];
    __shared__ int   ri[128];
    int row = blockIdx.x;
    int tid = threadIdx.x;
    const float* d = D + (size_t)row * NN;
    for (int m = tid; m < NN; m += 128) sd[m] = d[m];
    __syncthreads();
    for (int t = 0; t < KNB; t++) {
        float bv = 3.4e38f; int bi = NN;
        for (int m = tid; m < NN; m += 128) {
            float v = sd[m];
            if (v < bv || (v == bv && m < bi)) { bv = v; bi = m; }
        }
        rv[tid] = bv; ri[tid] = bi;
        __syncthreads();
        for (int s = 64; s > 0; s >>= 1) {
            if (tid < s) {
                if (rv[tid + s] < rv[tid] || (rv[tid + s] == rv[tid] && ri[tid + s] < ri[tid])) {
                    rv[tid] = rv[tid + s]; ri[tid] = ri[tid + s];
                }
            }
            __syncthreads();
        }
        if (tid == 0) { idx[row * KNB + t] = ri[0]; sd[ri[0]] = 3.4e38f; }
        __syncthreads();
    }
}

// ---------------- edge feature build -> bf16 hi/lo, zero-padded to Kpad ----------------
__global__ void de_edge_build_bf(const float* __restrict__ X, int ldx, int F, int Kpad,
                                 const int* __restrict__ idx,
                                 __nv_bfloat16* __restrict__ Eh, __nv_bfloat16* __restrict__ El) {
    __shared__ float sxi[256];
    int node = blockIdx.x;
    int b = node >> 9;
    const float* xi = X + (size_t)node * ldx;
    for (int f = threadIdx.x; f < F; f += blockDim.x) sxi[f] = xi[f];
    __syncthreads();
    for (int k = 0; k < KNB; k++) {
        int m = idx[node * KNB + k];
        const float* xj = X + (size_t)(b * NN + m) * ldx;
        size_t base = ((size_t)node * KNB + k) * Kpad;
        for (int f = threadIdx.x; f < Kpad; f += blockDim.x) {
            float v;
            if (f < F) v = sxi[f];
            else if (f < 2 * F) v = xj[f - F] - sxi[f - F];
            else v = 0.f;
            __nv_bfloat16 h = __float2bfloat16(v);
            Eh[base + f] = h;
            El[base + f] = __float2bfloat16(v - __bfloat162float(h));
        }
    }
}

// ---------------- flat fp32 -> bf16 hi/lo (weights) ----------------
__global__ void conv_flat(const float* __restrict__ X, int n,
                          __nv_bfloat16* __restrict__ H, __nv_bfloat16* __restrict__ L) {
    int i = blockIdx.x * blockDim.x + threadIdx.x;
    if (i >= n) return;
    float v = X[i];
    __nv_bfloat16 h = __float2bfloat16(v);
    H[i] = h;
    L[i] = __float2bfloat16(v - __bfloat162float(h));
}

// ---------------- padded matrix fp32 -> bf16 hi/lo ----------------
__global__ void conv_pad(const float* __restrict__ X, int ldx, int Kvalid, int Kpad, int M,
                         __nv_bfloat16* __restrict__ H, __nv_bfloat16* __restrict__ L) {
    int i = blockIdx.x * blockDim.x + threadIdx.x;
    if (i >= M * Kpad) return;
    int r = i / Kpad, c = i - r * Kpad;
    float v = (c < Kvalid) ? X[(size_t)r * ldx + c] : 0.f;
    __nv_bfloat16 h = __float2bfloat16(v);
    H[i] = h;
    L[i] = __float2bfloat16(v - __bfloat162float(h));
}

// ---------------- tensor-core GEMM: C = lrelu(A@W + b), split-bf16 (3 MMA) ----------------
// A: [M, Kpad] bf16 hi/lo row-major (pad cols zero). W: [K, N] bf16 hi/lo row-major.
// OUTMODE 0: write fp32 C [M, ldout] (cols < N).
// OUTMODE 1: write bf16 hi/lo [M, ldout] with cols in [N, ldout) zeroed.
#define BM 128
#define BN 64
#define BK 32

template<int OUTMODE>
__global__ __launch_bounds__(256)
void tc_gemm(const __nv_bfloat16* __restrict__ Ah, const __nv_bfloat16* __restrict__ Al,
             const __nv_bfloat16* __restrict__ Wh, const __nv_bfloat16* __restrict__ Wl,
             const float* __restrict__ bias,
             float* __restrict__ Cf, __nv_bfloat16* __restrict__ Ch, __nv_bfloat16* __restrict__ Cl,
             int M, int N, int K, int Kpad, int ldout)
{
    __shared__ __align__(16) char smem[35840];
    __nv_bfloat16 (*sAh)[BK + 8] = (__nv_bfloat16(*)[BK + 8])(smem);
    __nv_bfloat16 (*sAl)[BK + 8] = (__nv_bfloat16(*)[BK + 8])(smem + 10240);
    __nv_bfloat16 (*sWh)[BN + 8] = (__nv_bfloat16(*)[BN + 8])(smem + 20480);
    __nv_bfloat16 (*sWl)[BN + 8] = (__nv_bfloat16(*)[BN + 8])(smem + 25088);
    float (*sC)[BN + 4] = (float(*)[BN + 4])(smem);

    int m0 = blockIdx.y * BM;
    int n0 = blockIdx.x * BN;
    int tid = threadIdx.x;
    int warp = tid >> 5;
    int wm = warp >> 1;   // 0..3 -> 32-row slab
    int wn = warp & 1;    // 0..1 -> 32-col slab

    wmma::fragment<wmma::accumulator, 16, 16, 16, float> acc[2][2];
#pragma unroll
    for (int i = 0; i < 2; i++)
#pragma unroll
        for (int j = 0; j < 2; j++) wmma::fill_fragment(acc[i][j], 0.f);

    for (int k0 = 0; k0 < Kpad; k0 += BK) {
        // A tile: 128x32 bf16, vectorized (8 bf16 = 16B)
        for (int v = tid; v < BM * BK / 8; v += 256) {
            int r = v >> 2;
            int c = (v & 3) * 8;
            size_t gi = (size_t)(m0 + r) * Kpad + k0 + c;
            *(uint4*)&sAh[r][c] = *(const uint4*)&Ah[gi];
            *(uint4*)&sAl[r][c] = *(const uint4*)&Al[gi];
        }
        // W tile: 32x64, elementwise guarded (W is tiny, L2-resident)
        for (int v = tid; v < BK * BN; v += 256) {
            int r = v >> 6, c = v & 63;
            int k = k0 + r, n = n0 + c;
            bool in = (k < K) && (n < N);
            sWh[r][c] = in ? Wh[(size_t)k * N + n] : __float2bfloat16(0.f);
            sWl[r][c] = in ? Wl[(size_t)k * N + n] : __float2bfloat16(0.f);
        }
        __syncthreads();
#pragma unroll
        for (int kk = 0; kk < BK; kk += 16) {
            wmma::fragment<wmma::matrix_a, 16, 16, 16, __nv_bfloat16, wmma::row_major> ah[2], al[2];
            wmma::fragment<wmma::matrix_b, 16, 16, 16, __nv_bfloat16, wmma::row_major> bh[2], bl[2];
#pragma unroll
            for (int i = 0; i < 2; i++) {
                wmma::load_matrix_sync(ah[i], &sAh[wm * 32 + i * 16][kk], BK + 8);
                wmma::load_matrix_sync(al[i], &sAl[wm * 32 + i * 16][kk], BK + 8);
            }
#pragma unroll
            for (int j = 0; j < 2; j++) {
                wmma::load_matrix_sync(bh[j], &sWh[kk][wn * 32 + j * 16], BN + 8);
                wmma::load_matrix_sync(bl[j], &sWl[kk][wn * 32 + j * 16], BN + 8);
            }
#pragma unroll
            for (int i = 0; i < 2; i++)
#pragma unroll
                for (int j = 0; j < 2; j++) {
                    wmma::mma_sync(acc[i][j], ah[i], bh[j], acc[i][j]);
                    wmma::mma_sync(acc[i][j], al[i], bh[j], acc[i][j]);
                    wmma::mma_sync(acc[i][j], ah[i], bl[j], acc[i][j]);
                }
        }
        __syncthreads();
    }

    // epilogue via smem (overlaps load buffers; all reads done)
#pragma unroll
    for (int i = 0; i < 2; i++)
#pragma unroll
        for (int j = 0; j < 2; j++)
            wmma::store_matrix_sync(&sC[wm * 32 + i * 16][wn * 32 + j * 16], acc[i][j],
                                    BN + 4, wmma::mem_row_major);
    __syncthreads();

    for (int v = tid; v < BM * BN; v += 256) {
        int r = v >> 6, c = v & 63;
        int m = m0 + r, n = n0 + c;
        if (m >= M) continue;
        if (OUTMODE == 0) {
            if (n < N) {
                float val = lrelu(sC[r][c] + bias[n]);
                Cf[(size_t)m * ldout + n] = val;
            }
        } else {
            if (n < ldout) {
                float val = (n < N) ? lrelu(sC[r][c] + bias[n]) : 0.f;
                __nv_bfloat16 h = __float2bfloat16(val);
                Ch[(size_t)m * ldout + n] = h;
                Cl[(size_t)m * ldout + n] = __float2bfloat16(val - __bfloat162float(h));
            }
        }
    }
}

// ---------------- max over K edges -> CAT column block ----------------
__global__ void de_maxk(const float* __restrict__ H2, float* __restrict__ CAT, int colOff) {
    int i = blockIdx.x * blockDim.x + threadIdx.x;
    if (i >= NODES * 256) return;
    int node = i >> 8, c = i & 255;
    const float* h = H2 + ((size_t)node * KNB) * 256 + c;
    float m = h[0];
#pragma unroll
    for (int k = 1; k < KNB; k++) m = fmaxf(m, h[(size_t)k * 256]);
    CAT[(size_t)node * CATD + colOff + c] = m;
}

__global__ void de_copyx(const float* __restrict__ x, float* __restrict__ CAT) {
    int i = blockIdx.x * blockDim.x + threadIdx.x;
    if (i >= NODES * 6) return;
    int node = i / 6, f = i % 6;
    CAT[(size_t)node * CATD + f] = x[(size_t)node * 6 + f];
}

__global__ void de_mean(const float* __restrict__ H, float* __restrict__ G) {
    int b = blockIdx.x, c = threadIdx.x;
    float s = 0.f;
    for (int n = 0; n < NN; n++) s += H[((size_t)b * NN + n) * 256 + c];
    G[b * 256 + c] = s * (1.f / NN);
}

__global__ void de_head1(const float* __restrict__ G, const float* __restrict__ W,
                         const float* __restrict__ bias, float* __restrict__ T) {
    int b = blockIdx.x, j = threadIdx.x;
    float s = bias[j];
    for (int c = 0; c < 256; c++) s += G[b * 256 + c] * W[c * 128 + j];
    T[b * 128 + j] = lrelu(s);
}

__global__ void de_head2(const float* __restrict__ T, const float* __restrict__ W,
                         const float* __restrict__ bias, float* __restrict__ out) {
    int b = blockIdx.x, o = threadIdx.x;
    if (o >= 3) return;
    float s = bias[o];
    for (int j = 0; j < 128; j++) s += T[b * 128 + j] * W[j * 3 + o];
    out[b * 3 + o] = s;
}

// ---------------- launch ----------------
extern "C" void kernel_launch(void* const* d_in, const int* in_sizes, int n_in,
                              void* d_out, int out_size) {
    (void)in_sizes; (void)n_in; (void)out_size;
    const float* x = (const float*)d_in[0];
    const float* cw1[4], *cb1[4], *cw2[4], *cb2[4];
    for (int l = 0; l < 4; l++) {
        cw1[l] = (const float*)d_in[3 + 4 * l];
        cb1[l] = (const float*)d_in[4 + 4 * l];
        cw2[l] = (const float*)d_in[5 + 4 * l];
        cb2[l] = (const float*)d_in[6 + 4 * l];
    }
    const float* m1w1 = (const float*)d_in[19];
    const float* m1b1 = (const float*)d_in[20];
    const float* m1w2 = (const float*)d_in[21];
    const float* m1b2 = (const float*)d_in[22];
    const float* m2w1 = (const float*)d_in[23];
    const float* m2b1 = (const float*)d_in[24];
    const float* m2w2 = (const float*)d_in[25];
    const float* m2b2 = (const float*)d_in[26];

    float *D, *H2, *CAT, *X2, *G, *T;
    __nv_bfloat16 *Eh, *El, *H1h, *H1l, *CATh, *CATl, *W1h, *W1l, *W2h, *W2l;
    int* IDX;
    cudaGetSymbolAddress((void**)&D,    g_D);
    cudaGetSymbolAddress((void**)&Eh,   g_Eh);
    cudaGetSymbolAddress((void**)&El,   g_El);
    cudaGetSymbolAddress((void**)&H1h,  g_H1h);
    cudaGetSymbolAddress((void**)&H1l,  g_H1l);
    cudaGetSymbolAddress((void**)&H2,   g_H2);
    cudaGetSymbolAddress((void**)&CAT,  g_CAT);
    cudaGetSymbolAddress((void**)&CATh, g_CATh);
    cudaGetSymbolAddress((void**)&CATl, g_CATl);
    cudaGetSymbolAddress((void**)&X2,   g_X2);
    cudaGetSymbolAddress((void**)&IDX,  g_IDX);
    cudaGetSymbolAddress((void**)&G,    g_G);
    cudaGetSymbolAddress((void**)&T,    g_T);
    cudaGetSymbolAddress((void**)&W1h,  g_W1h);
    cudaGetSymbolAddress((void**)&W1l,  g_W1l);
    cudaGetSymbolAddress((void**)&W2h,  g_W2h);
    cudaGetSymbolAddress((void**)&W2l,  g_W2l);

    de_copyx<<<(NODES * 6 + 255) / 256, 256>>>(x, CAT);

    for (int l = 0; l < 4; l++) {
        const float* Xsrc;
        int ldx, F, off;
        if (l == 0) { Xsrc = x; ldx = 6; F = 6; off = 6; }
        else        { Xsrc = CAT + (6 + (l - 1) * 256); ldx = CATD; F = 256; off = 6 + l * 256; }
        int twoF = 2 * F;
        int Kpad1 = (l == 0) ? 32 : 512;

        de_sqnorm<<<(NODES + 255) / 256, 256>>>(Xsrc, ldx, F, X2);
        de_dist<<<dim3(8, 8, NB), 256>>>(Xsrc, ldx, F, X2, D);
        de_topk<<<NODES, 128>>>(D, IDX);

        conv_flat<<<(twoF * 336 + 255) / 256, 256>>>(cw1[l], twoF * 336, W1h, W1l);
        conv_flat<<<(336 * 256 + 255) / 256, 256>>>(cw2[l], 336 * 256, W2h, W2l);

        de_edge_build_bf<<<NODES, 256>>>(Xsrc, ldx, F, Kpad1, IDX, Eh, El);

        // gemm1: [EDGES, twoF] @ [twoF, 336] -> H1 hi/lo (ldout=352)
        tc_gemm<1><<<dim3(H1P / BN + (H1P % BN ? 1 : 0), EDGES / BM), 256>>>(
            Eh, El, W1h, W1l, cb1[l], nullptr, H1h, H1l, EDGES, 336, twoF, Kpad1, H1P);
        // gemm2: [EDGES, 336] @ [336, 256] -> H2 fp32
        tc_gemm<0><<<dim3(256 / BN, EDGES / BM), 256>>>(
            H1h, H1l, W2h, W2l, cb2[l], H2, nullptr, nullptr, EDGES, 256, 336, H1P, 256);

        de_maxk<<<(NODES * 256 + 255) / 256, 256>>>(H2, CAT, off);
    }

    // mlp1: [NODES,1030] -> 336 -> 256
    conv_flat<<<(CATD * 336 + 255) / 256, 256>>>(m1w1, CATD * 336, W1h, W1l);
    conv_flat<<<(336 * 256 + 255) / 256, 256>>>(m1w2, 336 * 256, W2h, W2l);
    conv_pad<<<((size_t)NODES * CATP + 255) / 256, 256>>>(CAT, CATD, CATD, CATP, NODES, CATh, CATl);

    tc_gemm<1><<<dim3(H1P / BN + (H1P % BN ? 1 : 0), NODES / BM), 256>>>(
        CATh, CATl, W1h, W1l, m1b1, nullptr, H1h, H1l, NODES, 336, CATD, CATP, H1P);
    tc_gemm<0><<<dim3(256 / BN, NODES / BM), 256>>>(
        H1h, H1l, W2h, W2l, m1b2, H2, nullptr, nullptr, NODES, 256, 336, H1P, 256);

    de_mean<<<NB, 256>>>(H2, G);
    de_head1<<<NB, 128>>>(G, m2w1, m2b1, T);
    de_head2<<<NB, 32>>>(T, m2w2, m2b2, (float*)d_out);
}

// round 5
// speedup vs baseline: 3.3656x; 1.7260x over previous
#include <cuda_runtime.h>
#include <cuda_bf16.h>
#include <mma.h>
#include <cstdint>

using namespace nvcuda;

#define NB 64
#define NN 512
#define KNB 8
#define NODES 32768
#define EDGES 262144
#define CATD 1030
#define CATP 1056
#define H1P  352    // 336 padded
#define PQLD 352    // P/Q row stride (fp32)

// ---------------- scratch ----------------
__device__ float g_D[(size_t)NODES * 512];
__device__ float g_P[(size_t)NODES * PQLD];
__device__ float g_Q[(size_t)NODES * PQLD];
__device__ __nv_bfloat16 g_Xh[(size_t)NODES * 256];
__device__ __nv_bfloat16 g_Xl[(size_t)NODES * 256];
__device__ float g_CAT[(size_t)NODES * CATD];
__device__ __nv_bfloat16 g_CATh[(size_t)NODES * CATP];
__device__ __nv_bfloat16 g_CATl[(size_t)NODES * CATP];
__device__ __nv_bfloat16 g_H1h[(size_t)NODES * H1P];
__device__ __nv_bfloat16 g_H1l[(size_t)NODES * H1P];
__device__ float g_H2[(size_t)NODES * 256];
__device__ float g_X2[NODES];
__device__ int   g_IDX[NODES * KNB];
__device__ float g_G[64 * 256];
__device__ float g_T[64 * 128];
__device__ __nv_bfloat16 g_Wdh[256 * 336];
__device__ __nv_bfloat16 g_Wdl[256 * 336];
__device__ __nv_bfloat16 g_Wbh[256 * 336];
__device__ __nv_bfloat16 g_Wbl[256 * 336];
__device__ __nv_bfloat16 g_W2ph[352 * 256];
__device__ __nv_bfloat16 g_W2pl[352 * 256];
__device__ __nv_bfloat16 g_W1h[1030 * 336];
__device__ __nv_bfloat16 g_W1l[1030 * 336];
__device__ float g_bzero[352];   // zero-initialized

__device__ __forceinline__ float lrelu(float v) { return (v >= 0.f) ? v : 0.01f * v; }

// ---------------- squared norms ----------------
__global__ void de_sqnorm(const float* __restrict__ X, int ldx, int F, float* __restrict__ x2) {
    int i = blockIdx.x * blockDim.x + threadIdx.x;
    if (i < NODES) {
        const float* r = X + (size_t)i * ldx;
        float s = 0.f;
        for (int f = 0; f < F; f++) { float v = r[f]; s += v * v; }
        x2[i] = s;
    }
}

// ---------------- pairwise distance (fp32, bit-stable kNN) ----------------
__global__ void de_dist(const float* __restrict__ X, int ldx, int F,
                        const float* __restrict__ x2, float* __restrict__ D) {
    __shared__ float As[16][68];
    __shared__ float Bs[16][68];
    int b  = blockIdx.z;
    const float* Xb = X + (size_t)b * NN * ldx;
    int n0 = blockIdx.y * 64, m0 = blockIdx.x * 64;
    int tx = threadIdx.x & 15, ty = threadIdx.x >> 4;
    float acc[4][4] = {};
    for (int k0 = 0; k0 < F; k0 += 16) {
        for (int i = threadIdx.x; i < 1024; i += 256) {
            int kk = i & 15, rr = i >> 4;
            int k = k0 + kk;
            As[kk][rr] = (k < F) ? Xb[(size_t)(n0 + rr) * ldx + k] : 0.f;
            Bs[kk][rr] = (k < F) ? Xb[(size_t)(m0 + rr) * ldx + k] : 0.f;
        }
        __syncthreads();
#pragma unroll
        for (int kk = 0; kk < 16; kk++) {
            float4 a4 = *(const float4*)&As[kk][ty * 4];
            float4 w4 = *(const float4*)&Bs[kk][tx * 4];
            float av[4] = {a4.x, a4.y, a4.z, a4.w};
            float wv[4] = {w4.x, w4.y, w4.z, w4.w};
#pragma unroll
            for (int i = 0; i < 4; i++)
#pragma unroll
                for (int j = 0; j < 4; j++) acc[i][j] += av[i] * wv[j];
        }
        __syncthreads();
    }
    int nb = b * NN;
#pragma unroll
    for (int i = 0; i < 4; i++) {
        int n = n0 + ty * 4 + i;
        float xn = x2[nb + n];
#pragma unroll
        for (int j = 0; j < 4; j++) {
            int m = m0 + tx * 4 + j;
            D[((size_t)(nb + n)) * NN + m] = xn + x2[nb + m] - 2.f * acc[i][j];
        }
    }
}

// ---------------- top-8 smallest, register/shuffle version (64 threads) ----------------
__global__ void de_topk2(const float* __restrict__ D, int* __restrict__ out) {
    int row = blockIdx.x;
    int tid = threadIdx.x;           // 0..63
    const float* d = D + (size_t)row * NN;
    float v[8];
#pragma unroll
    for (int j = 0; j < 8; j++) v[j] = d[tid + 64 * j];
    __shared__ float sv[2];
    __shared__ int   si[2];
    __shared__ int   schosen;
    for (int t = 0; t < KNB; t++) {
        float bv = v[0]; int bj = 0;
#pragma unroll
        for (int j = 1; j < 8; j++) if (v[j] < bv) { bv = v[j]; bj = j; }
        int bidx = tid + 64 * bj;
#pragma unroll
        for (int s = 16; s > 0; s >>= 1) {
            float ov = __shfl_down_sync(0xFFFFFFFFu, bv, s);
            int   oi = __shfl_down_sync(0xFFFFFFFFu, bidx, s);
            if (ov < bv || (ov == bv && oi < bidx)) { bv = ov; bidx = oi; }
        }
        if ((tid & 31) == 0) { sv[tid >> 5] = bv; si[tid >> 5] = bidx; }
        __syncthreads();
        if (tid == 0) {
            int w = (sv[1] < sv[0] || (sv[1] == sv[0] && si[1] < si[0])) ? 1 : 0;
            schosen = si[w];
            out[row * KNB + t] = si[w];
        }
        __syncthreads();
        int ch = schosen;
        if ((ch & 63) == tid) v[ch >> 6] = 3.4e38f;
        __syncthreads();
    }
}

// ---------------- fp32 -> bf16 hi/lo helpers ----------------
__global__ void conv_flat(const float* __restrict__ X, int n,
                          __nv_bfloat16* __restrict__ H, __nv_bfloat16* __restrict__ L) {
    int i = blockIdx.x * blockDim.x + threadIdx.x;
    if (i >= n) return;
    float v = X[i];
    __nv_bfloat16 h = __float2bfloat16(v);
    H[i] = h;
    L[i] = __float2bfloat16(v - __bfloat162float(h));
}

__global__ void conv_pad(const float* __restrict__ X, int ldx, int Kvalid, int Kpad, int M,
                         __nv_bfloat16* __restrict__ H, __nv_bfloat16* __restrict__ L) {
    int i = blockIdx.x * blockDim.x + threadIdx.x;
    if (i >= M * Kpad) return;
    int r = i / Kpad, c = i - r * Kpad;
    float v = (c < Kvalid) ? X[(size_t)r * ldx + c] : 0.f;
    __nv_bfloat16 h = __float2bfloat16(v);
    H[i] = h;
    L[i] = __float2bfloat16(v - __bfloat162float(h));
}

// ---------------- weight prep: Wd = W1top - W1bot, Wb = W1bot ----------------
__global__ void prep_wdb(const float* __restrict__ w1, int F,
                         __nv_bfloat16* __restrict__ Wdh, __nv_bfloat16* __restrict__ Wdl,
                         __nv_bfloat16* __restrict__ Wbh, __nv_bfloat16* __restrict__ Wbl) {
    int i = blockIdx.x * blockDim.x + threadIdx.x;
    if (i >= F * 336) return;
    float top = w1[i];
    float bot = w1[i + F * 336];
    float d = top - bot;
    __nv_bfloat16 dh = __float2bfloat16(d);
    Wdh[i] = dh; Wdl[i] = __float2bfloat16(d - __bfloat162float(dh));
    __nv_bfloat16 bh = __float2bfloat16(bot);
    Wbh[i] = bh; Wbl[i] = __float2bfloat16(bot - __bfloat162float(bh));
}

// ---------------- W2 padded to [352][256] ----------------
__global__ void prep_w2p(const float* __restrict__ w2,
                         __nv_bfloat16* __restrict__ H, __nv_bfloat16* __restrict__ L) {
    int i = blockIdx.x * blockDim.x + threadIdx.x;
    if (i >= 352 * 256) return;
    int k = i >> 8;
    float v = (k < 336) ? w2[i] : 0.f;
    __nv_bfloat16 h = __float2bfloat16(v);
    H[i] = h;
    L[i] = __float2bfloat16(v - __bfloat162float(h));
}

// ---------------- tensor-core GEMM (split-bf16, 3 MMA) ----------------
// OUTMODE 0: fp32 + bias + lrelu. 1: bf16 hi/lo + bias + lrelu, pad cols zeroed.
// 2: fp32 + bias, NO act, pad cols zeroed (for P/Q).
#define BM 128
#define BN 64
#define BK 32

template<int OUTMODE>
__global__ __launch_bounds__(256)
void tc_gemm(const __nv_bfloat16* __restrict__ Ah, const __nv_bfloat16* __restrict__ Al,
             const __nv_bfloat16* __restrict__ Wh, const __nv_bfloat16* __restrict__ Wl,
             const float* __restrict__ bias,
             float* __restrict__ Cf, __nv_bfloat16* __restrict__ Ch, __nv_bfloat16* __restrict__ Cl,
             int M, int N, int K, int Kpad, int ldout)
{
    __shared__ __align__(16) char smem[35840];
    __nv_bfloat16 (*sAh)[BK + 8] = (__nv_bfloat16(*)[BK + 8])(smem);
    __nv_bfloat16 (*sAl)[BK + 8] = (__nv_bfloat16(*)[BK + 8])(smem + 10240);
    __nv_bfloat16 (*sWh)[BN + 8] = (__nv_bfloat16(*)[BN + 8])(smem + 20480);
    __nv_bfloat16 (*sWl)[BN + 8] = (__nv_bfloat16(*)[BN + 8])(smem + 25088);
    float (*sC)[BN + 4] = (float(*)[BN + 4])(smem);

    int m0 = blockIdx.y * BM;
    int n0 = blockIdx.x * BN;
    int tid = threadIdx.x;
    int warp = tid >> 5;
    int wm = warp >> 1;
    int wn = warp & 1;

    wmma::fragment<wmma::accumulator, 16, 16, 16, float> acc[2][2];
#pragma unroll
    for (int i = 0; i < 2; i++)
#pragma unroll
        for (int j = 0; j < 2; j++) wmma::fill_fragment(acc[i][j], 0.f);

    for (int k0 = 0; k0 < Kpad; k0 += BK) {
        for (int v = tid; v < BM * BK / 8; v += 256) {
            int r = v >> 2;
            int c = (v & 3) * 8;
            size_t gi = (size_t)(m0 + r) * Kpad + k0 + c;
            *(uint4*)&sAh[r][c] = *(const uint4*)&Ah[gi];
            *(uint4*)&sAl[r][c] = *(const uint4*)&Al[gi];
        }
        for (int v = tid; v < BK * BN; v += 256) {
            int r = v >> 6, c = v & 63;
            int k = k0 + r, n = n0 + c;
            bool in = (k < K) && (n < N);
            sWh[r][c] = in ? Wh[(size_t)k * N + n] : __float2bfloat16(0.f);
            sWl[r][c] = in ? Wl[(size_t)k * N + n] : __float2bfloat16(0.f);
        }
        __syncthreads();
#pragma unroll
        for (int kk = 0; kk < BK; kk += 16) {
            wmma::fragment<wmma::matrix_a, 16, 16, 16, __nv_bfloat16, wmma::row_major> ah[2], al[2];
            wmma::fragment<wmma::matrix_b, 16, 16, 16, __nv_bfloat16, wmma::row_major> bh[2], bl[2];
#pragma unroll
            for (int i = 0; i < 2; i++) {
                wmma::load_matrix_sync(ah[i], &sAh[wm * 32 + i * 16][kk], BK + 8);
                wmma::load_matrix_sync(al[i], &sAl[wm * 32 + i * 16][kk], BK + 8);
            }
#pragma unroll
            for (int j = 0; j < 2; j++) {
                wmma::load_matrix_sync(bh[j], &sWh[kk][wn * 32 + j * 16], BN + 8);
                wmma::load_matrix_sync(bl[j], &sWl[kk][wn * 32 + j * 16], BN + 8);
            }
#pragma unroll
            for (int i = 0; i < 2; i++)
#pragma unroll
                for (int j = 0; j < 2; j++) {
                    wmma::mma_sync(acc[i][j], ah[i], bh[j], acc[i][j]);
                    wmma::mma_sync(acc[i][j], al[i], bh[j], acc[i][j]);
                    wmma::mma_sync(acc[i][j], ah[i], bl[j], acc[i][j]);
                }
        }
        __syncthreads();
    }

#pragma unroll
    for (int i = 0; i < 2; i++)
#pragma unroll
        for (int j = 0; j < 2; j++)
            wmma::store_matrix_sync(&sC[wm * 32 + i * 16][wn * 32 + j * 16], acc[i][j],
                                    BN + 4, wmma::mem_row_major);
    __syncthreads();

    for (int v = tid; v < BM * BN; v += 256) {
        int r = v >> 6, c = v & 63;
        int m = m0 + r, n = n0 + c;
        if (m >= M) continue;
        if (OUTMODE == 0) {
            if (n < N) Cf[(size_t)m * ldout + n] = lrelu(sC[r][c] + bias[n]);
        } else if (OUTMODE == 1) {
            if (n < ldout) {
                float val = (n < N) ? lrelu(sC[r][c] + bias[n]) : 0.f;
                __nv_bfloat16 h = __float2bfloat16(val);
                Ch[(size_t)m * ldout + n] = h;
                Cl[(size_t)m * ldout + n] = __float2bfloat16(val - __bfloat162float(h));
            }
        } else {
            if (n < ldout) {
                float val = (n < N) ? (sC[r][c] + bias[n]) : 0.f;
                Cf[(size_t)m * ldout + n] = val;
            }
        }
    }
}

// ---------------- fused GEMM2 + bias + lrelu + max-agg ----------------
// Per block: 8 nodes (64 edge rows). A[r][c] = lrelu(P[i][c] + Q[j][c]).
// A resident in smem (bf16 hi/lo), W2 streamed. Out: max over k, -> CAT.
#define F_LDA 368
#define F_LDW 264
#define F_SMEM 128000

__global__ __launch_bounds__(256)
void de_fused2(const float* __restrict__ P, const float* __restrict__ Q,
               const int* __restrict__ idx,
               const __nv_bfloat16* __restrict__ W2h, const __nv_bfloat16* __restrict__ W2l,
               const float* __restrict__ b2, float* __restrict__ CAT, int colOff)
{
    extern __shared__ __align__(16) char smem[];
    __nv_bfloat16* sAh = (__nv_bfloat16*)smem;                 // 64 x 368
    __nv_bfloat16* sAl = sAh + 64 * F_LDA;                     // 64 x 368
    __nv_bfloat16* sWh = (__nv_bfloat16*)(smem + 94208);       // 32 x 264
    __nv_bfloat16* sWl = sWh + 32 * F_LDW;
    float* sC = (float*)smem;                                  // reuse, ld 260

    int node0 = blockIdx.x * 8;
    int gbase = (node0 >> 9) << 9;
    int tid = threadIdx.x;
    int warp = tid >> 5;
    int wm = warp & 1;     // row slab (32)
    int wn = warp >> 1;    // col slab (64)

    // phase 1: build A (64 x 352)
    for (int v = tid; v < 64 * 88; v += 256) {
        int r = v / 88, c = (v - r * 88) * 4;
        int i = node0 + (r >> 3);
        int j = gbase + idx[i * KNB + (r & 7)];
        float4 p = *(const float4*)&P[(size_t)i * PQLD + c];
        float4 q = *(const float4*)&Q[(size_t)j * PQLD + c];
        float s[4] = { lrelu(p.x + q.x), lrelu(p.y + q.y), lrelu(p.z + q.z), lrelu(p.w + q.w) };
#pragma unroll
        for (int u = 0; u < 4; u++) {
            __nv_bfloat16 h = __float2bfloat16(s[u]);
            sAh[r * F_LDA + c + u] = h;
            sAl[r * F_LDA + c + u] = __float2bfloat16(s[u] - __bfloat162float(h));
        }
    }
    __syncthreads();

    // phase 2: A @ W2, acc over full N=256
    wmma::fragment<wmma::accumulator, 16, 16, 16, float> acc[2][4];
#pragma unroll
    for (int i = 0; i < 2; i++)
#pragma unroll
        for (int j = 0; j < 4; j++) wmma::fill_fragment(acc[i][j], 0.f);

    for (int k0 = 0; k0 < 352; k0 += 32) {
        for (int v = tid; v < 32 * 32; v += 256) {   // 32 rows x 32 vec8
            int r = v >> 5, c = (v & 31) * 8;
            *(uint4*)&sWh[r * F_LDW + c] = *(const uint4*)&W2h[(size_t)(k0 + r) * 256 + c];
            *(uint4*)&sWl[r * F_LDW + c] = *(const uint4*)&W2l[(size_t)(k0 + r) * 256 + c];
        }
        __syncthreads();
#pragma unroll
        for (int kk = 0; kk < 32; kk += 16) {
            wmma::fragment<wmma::matrix_a, 16, 16, 16, __nv_bfloat16, wmma::row_major> ah[2], al[2];
#pragma unroll
            for (int i = 0; i < 2; i++) {
                wmma::load_matrix_sync(ah[i], &sAh[(wm * 32 + i * 16) * F_LDA + k0 + kk], F_LDA);
                wmma::load_matrix_sync(al[i], &sAl[(wm * 32 + i * 16) * F_LDA + k0 + kk], F_LDA);
            }
#pragma unroll
            for (int j = 0; j < 4; j++) {
                wmma::fragment<wmma::matrix_b, 16, 16, 16, __nv_bfloat16, wmma::row_major> bh, bl;
                wmma::load_matrix_sync(bh, &sWh[kk * F_LDW + wn * 64 + j * 16], F_LDW);
                wmma::load_matrix_sync(bl, &sWl[kk * F_LDW + wn * 64 + j * 16], F_LDW);
#pragma unroll
                for (int i = 0; i < 2; i++) {
                    wmma::mma_sync(acc[i][j], ah[i], bh, acc[i][j]);
                    wmma::mma_sync(acc[i][j], al[i], bh, acc[i][j]);
                    wmma::mma_sync(acc[i][j], ah[i], bl, acc[i][j]);
                }
            }
        }
        __syncthreads();
    }

    // phase 3: store C, then max over k + bias + lrelu
#pragma unroll
    for (int i = 0; i < 2; i++)
#pragma unroll
        for (int j = 0; j < 4; j++)
            wmma::store_matrix_sync(&sC[(wm * 32 + i * 16) * 260 + wn * 64 + j * 16], acc[i][j],
                                    260, wmma::mem_row_major);
    __syncthreads();

    for (int v = tid; v < 8 * 256; v += 256) {
        int ln = v >> 8, c = v & 255;
        float m = sC[(ln * 8) * 260 + c];
#pragma unroll
        for (int k = 1; k < KNB; k++) m = fmaxf(m, sC[(ln * 8 + k) * 260 + c]);
        CAT[(size_t)(node0 + ln) * CATD + colOff + c] = lrelu(m + b2[c]);
    }
}

// ---------------- misc ----------------
__global__ void de_copyx(const float* __restrict__ x, float* __restrict__ CAT) {
    int i = blockIdx.x * blockDim.x + threadIdx.x;
    if (i >= NODES * 6) return;
    int node = i / 6, f = i % 6;
    CAT[(size_t)node * CATD + f] = x[(size_t)node * 6 + f];
}

__global__ void de_mean(const float* __restrict__ H, float* __restrict__ G) {
    int b = blockIdx.x, c = threadIdx.x;
    float s = 0.f;
    for (int n = 0; n < NN; n++) s += H[((size_t)b * NN + n) * 256 + c];
    G[b * 256 + c] = s * (1.f / NN);
}

__global__ void de_head1(const float* __restrict__ G, const float* __restrict__ W,
                         const float* __restrict__ bias, float* __restrict__ T) {
    int b = blockIdx.x, j = threadIdx.x;
    float s = bias[j];
    for (int c = 0; c < 256; c++) s += G[b * 256 + c] * W[c * 128 + j];
    T[b * 128 + j] = lrelu(s);
}

__global__ void de_head2(const float* __restrict__ T, const float* __restrict__ W,
                         const float* __restrict__ bias, float* __restrict__ out) {
    int b = blockIdx.x, o = threadIdx.x;
    if (o >= 3) return;
    float s = bias[o];
    for (int j = 0; j < 128; j++) s += T[b * 128 + j] * W[j * 3 + o];
    out[b * 3 + o] = s;
}

// ---------------- launch ----------------
extern "C" void kernel_launch(void* const* d_in, const int* in_sizes, int n_in,
                              void* d_out, int out_size) {
    (void)in_sizes; (void)n_in; (void)out_size;
    const float* x = (const float*)d_in[0];
    const float* cw1[4], *cb1[4], *cw2[4], *cb2[4];
    for (int l = 0; l < 4; l++) {
        cw1[l] = (const float*)d_in[3 + 4 * l];
        cb1[l] = (const float*)d_in[4 + 4 * l];
        cw2[l] = (const float*)d_in[5 + 4 * l];
        cb2[l] = (const float*)d_in[6 + 4 * l];
    }
    const float* m1w1 = (const float*)d_in[19];
    const float* m1b1 = (const float*)d_in[20];
    const float* m1w2 = (const float*)d_in[21];
    const float* m1b2 = (const float*)d_in[22];
    const float* m2w1 = (const float*)d_in[23];
    const float* m2b1 = (const float*)d_in[24];
    const float* m2w2 = (const float*)d_in[25];
    const float* m2b2 = (const float*)d_in[26];

    float *D, *P, *Q, *CAT, *X2, *G, *T, *H2, *BZ;
    __nv_bfloat16 *Xh, *Xl, *CATh, *CATl, *H1h, *H1l;
    __nv_bfloat16 *Wdh, *Wdl, *Wbh, *Wbl, *W2ph, *W2pl, *W1h, *W1l;
    int* IDX;
    cudaGetSymbolAddress((void**)&D,    g_D);
    cudaGetSymbolAddress((void**)&P,    g_P);
    cudaGetSymbolAddress((void**)&Q,    g_Q);
    cudaGetSymbolAddress((void**)&Xh,   g_Xh);
    cudaGetSymbolAddress((void**)&Xl,   g_Xl);
    cudaGetSymbolAddress((void**)&CAT,  g_CAT);
    cudaGetSymbolAddress((void**)&CATh, g_CATh);
    cudaGetSymbolAddress((void**)&CATl, g_CATl);
    cudaGetSymbolAddress((void**)&H1h,  g_H1h);
    cudaGetSymbolAddress((void**)&H1l,  g_H1l);
    cudaGetSymbolAddress((void**)&H2,   g_H2);
    cudaGetSymbolAddress((void**)&X2,   g_X2);
    cudaGetSymbolAddress((void**)&IDX,  g_IDX);
    cudaGetSymbolAddress((void**)&G,    g_G);
    cudaGetSymbolAddress((void**)&T,    g_T);
    cudaGetSymbolAddress((void**)&Wdh,  g_Wdh);
    cudaGetSymbolAddress((void**)&Wdl,  g_Wdl);
    cudaGetSymbolAddress((void**)&Wbh,  g_Wbh);
    cudaGetSymbolAddress((void**)&Wbl,  g_Wbl);
    cudaGetSymbolAddress((void**)&W2ph, g_W2ph);
    cudaGetSymbolAddress((void**)&W2pl, g_W2pl);
    cudaGetSymbolAddress((void**)&W1h,  g_W1h);
    cudaGetSymbolAddress((void**)&W1l,  g_W1l);
    cudaGetSymbolAddress((void**)&BZ,   g_bzero);

    cudaFuncSetAttribute(de_fused2, cudaFuncAttributeMaxDynamicSharedMemorySize, F_SMEM);

    de_copyx<<<(NODES * 6 + 255) / 256, 256>>>(x, CAT);

    for (int l = 0; l < 4; l++) {
        const float* Xsrc;
        int ldx, F, off, Kpad;
        if (l == 0) { Xsrc = x; ldx = 6; F = 6; off = 6; Kpad = 32; }
        else { Xsrc = CAT + (6 + (l - 1) * 256); ldx = CATD; F = 256; off = 6 + l * 256; Kpad = 256; }

        de_sqnorm<<<(NODES + 255) / 256, 256>>>(Xsrc, ldx, F, X2);
        de_dist<<<dim3(8, 8, NB), 256>>>(Xsrc, ldx, F, X2, D);
        de_topk2<<<NODES, 64>>>(D, IDX);

        // weight prep
        prep_wdb<<<(F * 336 + 255) / 256, 256>>>(cw1[l], F, Wdh, Wdl, Wbh, Wbl);
        prep_w2p<<<(352 * 256 + 255) / 256, 256>>>(cw2[l], W2ph, W2pl);

        // layer input -> bf16 hi/lo
        conv_pad<<<((size_t)NODES * Kpad + 255) / 256, 256>>>(Xsrc, ldx, F, Kpad, NODES, Xh, Xl);

        // P = X @ (W1top - W1bot) + b1 ; Q = X @ W1bot (fp32, ld 352, zero-padded)
        tc_gemm<2><<<dim3(6, NODES / BM), 256>>>(Xh, Xl, Wdh, Wdl, cb1[l],
                                                 P, nullptr, nullptr, NODES, 336, F, Kpad, PQLD);
        tc_gemm<2><<<dim3(6, NODES / BM), 256>>>(Xh, Xl, Wbh, Wbl, BZ,
                                                 Q, nullptr, nullptr, NODES, 336, F, Kpad, PQLD);

        // fused GEMM2 + max-agg -> CAT
        de_fused2<<<NODES / 8, 256, F_SMEM>>>(P, Q, IDX, W2ph, W2pl, cb2[l], CAT, off);
    }

    // mlp1: [NODES,1030] -> 336 -> 256
    conv_flat<<<(CATD * 336 + 255) / 256, 256>>>(m1w1, CATD * 336, W1h, W1l);
    prep_w2p<<<(352 * 256 + 255) / 256, 256>>>(m1w2, W2ph, W2pl);
    conv_pad<<<((size_t)NODES * CATP + 255) / 256, 256>>>(CAT, CATD, CATD, CATP, NODES, CATh, CATl);

    tc_gemm<1><<<dim3(6, NODES / BM), 256>>>(CATh, CATl, W1h, W1l, m1b1,
                                             nullptr, H1h, H1l, NODES, 336, CATD, CATP, H1P);
    tc_gemm<0><<<dim3(4, NODES / BM), 256>>>(H1h, H1l, W2ph, W2pl, m1b2,
                                             H2, nullptr, nullptr, NODES, 256, 336, H1P, 256);

    de_mean<<<NB, 256>>>(H2, G);
    de_head1<<<NB, 128>>>(G, m2w1, m2b1, T);
    de_head2<<<NB, 32>>>(T, m2w2, m2b2, (float*)d_out);
}

// round 7
// speedup vs baseline: 4.0928x; 1.2161x over previous
#include <cuda_runtime.h>
#include <cuda_bf16.h>
#include <mma.h>
#include <cstdint>

using namespace nvcuda;

#define NB 64
#define NN 512
#define KNB 8
#define NODES 32768
#define CATD 1030
#define CATP 1056
#define H1P  352
#define PQLD 704    // [P(336) pad16 | Q(336) pad16]

// ---------------- scratch ----------------
__device__ float g_D[(size_t)NODES * 512];
__device__ float g_PQ[(size_t)NODES * PQLD];
__device__ __nv_bfloat16 g_Xh[(size_t)NODES * 256];
__device__ __nv_bfloat16 g_Xl[(size_t)NODES * 256];
__device__ float g_CAT[(size_t)NODES * CATD];
__device__ __nv_bfloat16 g_CATh[(size_t)NODES * CATP];
__device__ __nv_bfloat16 g_CATl[(size_t)NODES * CATP];
__device__ __nv_bfloat16 g_H1h[(size_t)NODES * H1P];
__device__ __nv_bfloat16 g_H1l[(size_t)NODES * H1P];
__device__ float g_H2[(size_t)NODES * 256];
__device__ float g_X2[NODES];
__device__ int   g_IDX[NODES * KNB];
__device__ float g_G[64 * 256];
__device__ float g_T[64 * 128];
__device__ __nv_bfloat16 g_Wch[256 * PQLD];   // combined [F, 704] hi
__device__ __nv_bfloat16 g_Wcl[256 * PQLD];   // combined lo
__device__ float g_bc[PQLD];
__device__ __nv_bfloat16 g_W2ph[352 * 256];
__device__ __nv_bfloat16 g_W2pl[352 * 256];
__device__ __nv_bfloat16 g_W1h[1030 * 336];
__device__ __nv_bfloat16 g_W1l[1030 * 336];

__device__ __forceinline__ float lrelu(float v) { return (v >= 0.f) ? v : 0.01f * v; }

// ---------------- squared norms ----------------
__global__ void de_sqnorm(const float* __restrict__ X, int ldx, int F, float* __restrict__ x2) {
    int i = blockIdx.x * blockDim.x + threadIdx.x;
    if (i < NODES) {
        const float* r = X + (size_t)i * ldx;
        float s = 0.f;
        for (int f = 0; f < F; f++) { float v = r[f]; s += v * v; }
        x2[i] = s;
    }
}

// ---------------- pairwise distance, 128x128 tile / 8x8 micro (fp32) ----------------
__global__ __launch_bounds__(256)
void de_dist2(const float* __restrict__ X, int ldx, int F,
              const float* __restrict__ x2, float* __restrict__ D) {
    __shared__ float As[16][136];
    __shared__ float Bs[16][136];
    int b = blockIdx.z;
    const float* Xb = X + (size_t)b * NN * ldx;
    int n0 = blockIdx.y * 128, m0 = blockIdx.x * 128;
    int tx = threadIdx.x & 15, ty = threadIdx.x >> 4;
    float acc[8][8] = {};
    for (int k0 = 0; k0 < F; k0 += 16) {
        for (int i = threadIdx.x; i < 2048; i += 256) {
            int kk = i & 15, rr = i >> 4;
            int k = k0 + kk;
            As[kk][rr] = (k < F) ? Xb[(size_t)(n0 + rr) * ldx + k] : 0.f;
            Bs[kk][rr] = (k < F) ? Xb[(size_t)(m0 + rr) * ldx + k] : 0.f;
        }
        __syncthreads();
#pragma unroll
        for (int kk = 0; kk < 16; kk++) {
            float av[8], wv[8];
            *(float4*)&av[0] = *(const float4*)&As[kk][ty * 8];
            *(float4*)&av[4] = *(const float4*)&As[kk][ty * 8 + 4];
            *(float4*)&wv[0] = *(const float4*)&Bs[kk][tx * 8];
            *(float4*)&wv[4] = *(const float4*)&Bs[kk][tx * 8 + 4];
#pragma unroll
            for (int i = 0; i < 8; i++)
#pragma unroll
                for (int j = 0; j < 8; j++) acc[i][j] += av[i] * wv[j];
        }
        __syncthreads();
    }
    int nb = b * NN;
#pragma unroll
    for (int i = 0; i < 8; i++) {
        int n = n0 + ty * 8 + i;
        float xn = x2[nb + n];
#pragma unroll
        for (int j = 0; j < 8; j++) {
            int m = m0 + tx * 8 + j;
            D[((size_t)(nb + n)) * NN + m] = xn + x2[nb + m] - 2.f * acc[i][j];
        }
    }
}

// ---------------- top-8 smallest (64 threads, registers + shuffle) ----------------
__global__ void de_topk2(const float* __restrict__ D, int* __restrict__ out) {
    int row = blockIdx.x;
    int tid = threadIdx.x;
    const float* d = D + (size_t)row * NN;
    float v[8];
#pragma unroll
    for (int j = 0; j < 8; j++) v[j] = d[tid + 64 * j];
    __shared__ float sv[2];
    __shared__ int   si[2];
    __shared__ int   schosen;
    for (int t = 0; t < KNB; t++) {
        float bv = v[0]; int bj = 0;
#pragma unroll
        for (int j = 1; j < 8; j++) if (v[j] < bv) { bv = v[j]; bj = j; }
        int bidx = tid + 64 * bj;
#pragma unroll
        for (int s = 16; s > 0; s >>= 1) {
            float ov = __shfl_down_sync(0xFFFFFFFFu, bv, s);
            int   oi = __shfl_down_sync(0xFFFFFFFFu, bidx, s);
            if (ov < bv || (ov == bv && oi < bidx)) { bv = ov; bidx = oi; }
        }
        if ((tid & 31) == 0) { sv[tid >> 5] = bv; si[tid >> 5] = bidx; }
        __syncthreads();
        if (tid == 0) {
            int w = (sv[1] < sv[0] || (sv[1] == sv[0] && si[1] < si[0])) ? 1 : 0;
            schosen = si[w];
            out[row * KNB + t] = si[w];
        }
        __syncthreads();
        int ch = schosen;
        if ((ch & 63) == tid) v[ch >> 6] = 3.4e38f;
        __syncthreads();
    }
}

// ---------------- fp32 -> bf16 hi/lo helpers ----------------
__global__ void conv_flat(const float* __restrict__ X, int n,
                          __nv_bfloat16* __restrict__ H, __nv_bfloat16* __restrict__ L) {
    int i = blockIdx.x * blockDim.x + threadIdx.x;
    if (i >= n) return;
    float v = X[i];
    __nv_bfloat16 h = __float2bfloat16(v);
    H[i] = h;
    L[i] = __float2bfloat16(v - __bfloat162float(h));
}

__global__ void conv_pad(const float* __restrict__ X, int ldx, int Kvalid, int Kpad, int M,
                         __nv_bfloat16* __restrict__ H, __nv_bfloat16* __restrict__ L) {
    int i = blockIdx.x * blockDim.x + threadIdx.x;
    if (i >= M * Kpad) return;
    int r = i / Kpad, c = i - r * Kpad;
    float v = (c < Kvalid) ? X[(size_t)r * ldx + c] : 0.f;
    __nv_bfloat16 h = __float2bfloat16(v);
    H[i] = h;
    L[i] = __float2bfloat16(v - __bfloat162float(h));
}

// ---------------- combined weight prep: [F, 704] = [Wtop-Wbot | 0 | Wbot | 0] ----------------
__global__ void prep_wcomb(const float* __restrict__ w1, const float* __restrict__ b1, int F,
                           __nv_bfloat16* __restrict__ Wh, __nv_bfloat16* __restrict__ Wl,
                           float* __restrict__ bc) {
    int i = blockIdx.x * blockDim.x + threadIdx.x;
    if (i >= F * PQLD) return;
    int k = i / PQLD, c = i - k * PQLD;
    float v = 0.f;
    if (c < 336) v = w1[k * 336 + c] - w1[(F + k) * 336 + c];
    else if (c >= 352 && c < 688) v = w1[(size_t)(F + k) * 336 + (c - 352)];
    __nv_bfloat16 h = __float2bfloat16(v);
    Wh[i] = h;
    Wl[i] = __float2bfloat16(v - __bfloat162float(h));
    if (k == 0) bc[c] = (c < 336) ? b1[c] : 0.f;
}

// ---------------- W2 padded to [352][256] hi/lo ----------------
__global__ void prep_w2p(const float* __restrict__ w2,
                         __nv_bfloat16* __restrict__ H, __nv_bfloat16* __restrict__ L) {
    int i = blockIdx.x * blockDim.x + threadIdx.x;
    if (i >= 352 * 256) return;
    int k = i >> 8;
    float v = (k < 336) ? w2[i] : 0.f;
    __nv_bfloat16 h = __float2bfloat16(v);
    H[i] = h;
    L[i] = __float2bfloat16(v - __bfloat162float(h));
}

// ---------------- tensor-core GEMM (split-bf16, 3 MMA) ----------------
#define BM 128
#define BN 64
#define BK 32

template<int OUTMODE>
__global__ __launch_bounds__(256)
void tc_gemm(const __nv_bfloat16* __restrict__ Ah, const __nv_bfloat16* __restrict__ Al,
             const __nv_bfloat16* __restrict__ Wh, const __nv_bfloat16* __restrict__ Wl,
             const float* __restrict__ bias,
             float* __restrict__ Cf, __nv_bfloat16* __restrict__ Ch, __nv_bfloat16* __restrict__ Cl,
             int M, int N, int K, int Kpad, int ldout)
{
    __shared__ __align__(16) char smem[35840];
    __nv_bfloat16 (*sAh)[BK + 8] = (__nv_bfloat16(*)[BK + 8])(smem);
    __nv_bfloat16 (*sAl)[BK + 8] = (__nv_bfloat16(*)[BK + 8])(smem + 10240);
    __nv_bfloat16 (*sWh)[BN + 8] = (__nv_bfloat16(*)[BN + 8])(smem + 20480);
    __nv_bfloat16 (*sWl)[BN + 8] = (__nv_bfloat16(*)[BN + 8])(smem + 25088);
    float (*sC)[BN + 4] = (float(*)[BN + 4])(smem);

    int m0 = blockIdx.y * BM;
    int n0 = blockIdx.x * BN;
    int tid = threadIdx.x;
    int warp = tid >> 5;
    int wm = warp >> 1;
    int wn = warp & 1;

    wmma::fragment<wmma::accumulator, 16, 16, 16, float> acc[2][2];
#pragma unroll
    for (int i = 0; i < 2; i++)
#pragma unroll
        for (int j = 0; j < 2; j++) wmma::fill_fragment(acc[i][j], 0.f);

    for (int k0 = 0; k0 < Kpad; k0 += BK) {
        for (int v = tid; v < BM * BK / 8; v += 256) {
            int r = v >> 2;
            int c = (v & 3) * 8;
            size_t gi = (size_t)(m0 + r) * Kpad + k0 + c;
            *(uint4*)&sAh[r][c] = *(const uint4*)&Ah[gi];
            *(uint4*)&sAl[r][c] = *(const uint4*)&Al[gi];
        }
        for (int v = tid; v < BK * BN; v += 256) {
            int r = v >> 6, c = v & 63;
            int k = k0 + r, n = n0 + c;
            bool in = (k < K) && (n < N);
            sWh[r][c] = in ? Wh[(size_t)k * N + n] : __float2bfloat16(0.f);
            sWl[r][c] = in ? Wl[(size_t)k * N + n] : __float2bfloat16(0.f);
        }
        __syncthreads();
#pragma unroll
        for (int kk = 0; kk < BK; kk += 16) {
            wmma::fragment<wmma::matrix_a, 16, 16, 16, __nv_bfloat16, wmma::row_major> ah[2], al[2];
            wmma::fragment<wmma::matrix_b, 16, 16, 16, __nv_bfloat16, wmma::row_major> bh[2], bl[2];
#pragma unroll
            for (int i = 0; i < 2; i++) {
                wmma::load_matrix_sync(ah[i], &sAh[wm * 32 + i * 16][kk], BK + 8);
                wmma::load_matrix_sync(al[i], &sAl[wm * 32 + i * 16][kk], BK + 8);
            }
#pragma unroll
            for (int j = 0; j < 2; j++) {
                wmma::load_matrix_sync(bh[j], &sWh[kk][wn * 32 + j * 16], BN + 8);
                wmma::load_matrix_sync(bl[j], &sWl[kk][wn * 32 + j * 16], BN + 8);
            }
#pragma unroll
            for (int i = 0; i < 2; i++)
#pragma unroll
                for (int j = 0; j < 2; j++) {
                    wmma::mma_sync(acc[i][j], ah[i], bh[j], acc[i][j]);
                    wmma::mma_sync(acc[i][j], al[i], bh[j], acc[i][j]);
                    wmma::mma_sync(acc[i][j], ah[i], bl[j], acc[i][j]);
                }
        }
        __syncthreads();
    }

#pragma unroll
    for (int i = 0; i < 2; i++)
#pragma unroll
        for (int j = 0; j < 2; j++)
            wmma::store_matrix_sync(&sC[wm * 32 + i * 16][wn * 32 + j * 16], acc[i][j],
                                    BN + 4, wmma::mem_row_major);
    __syncthreads();

    for (int v = tid; v < BM * BN; v += 256) {
        int r = v >> 6, c = v & 63;
        int m = m0 + r, n = n0 + c;
        if (m >= M) continue;
        if (OUTMODE == 0) {
            if (n < N) Cf[(size_t)m * ldout + n] = lrelu(sC[r][c] + bias[n]);
        } else if (OUTMODE == 1) {
            if (n < ldout) {
                float val = (n < N) ? lrelu(sC[r][c] + bias[n]) : 0.f;
                __nv_bfloat16 h = __float2bfloat16(val);
                Ch[(size_t)m * ldout + n] = h;
                Cl[(size_t)m * ldout + n] = __float2bfloat16(val - __bfloat162float(h));
            }
        } else {
            if (n < ldout) {
                float val = (n < N) ? (sC[r][c] + bias[n]) : 0.f;
                Cf[(size_t)m * ldout + n] = val;
            }
        }
    }
}

// ---------------- fused GEMM2 + bias + lrelu + max-agg (16 nodes / 128 edge rows) ----------------
#define F_LDA 368
#define F_LDW 264
// sAh: 128*368*2 = 94208 ; sAl: 94208 ; sWh: 32*264*2 = 16896 ; sWl: 16896
#define F2_SMEM (94208 * 2 + 16896 * 2)

__global__ __launch_bounds__(512)
void de_fused2(const float* __restrict__ PQ,
               const int* __restrict__ idx,
               const __nv_bfloat16* __restrict__ W2h, const __nv_bfloat16* __restrict__ W2l,
               const float* __restrict__ b2, float* __restrict__ CAT, int colOff)
{
    extern __shared__ __align__(16) char smem[];
    __nv_bfloat16* sAh = (__nv_bfloat16*)smem;                   // 128 x 368
    __nv_bfloat16* sAl = sAh + 128 * F_LDA;
    __nv_bfloat16* sWh = (__nv_bfloat16*)(smem + 94208 * 2);     // 32 x 264
    __nv_bfloat16* sWl = sWh + 32 * F_LDW;
    float* sC = (float*)smem;                                    // reuse, ld 264

    int node0 = blockIdx.x * 16;
    int gbase = (node0 >> 9) << 9;
    int tid = threadIdx.x;
    int warp = tid >> 5;
    int wm = warp & 3;     // 4 row slabs of 32
    int wn = warp >> 2;    // 4 col slabs of 64

    // phase 1: A[r][c] = lrelu(P[i][c] + Q[j][c]), 128 x 352 (+pad16 zero)
    for (int v = tid; v < 128 * 88; v += 512) {
        int r = v / 88, c = (v - r * 88) * 4;
        int i = node0 + (r >> 3);
        int j = gbase + idx[i * KNB + (r & 7)];
        float4 p = *(const float4*)&PQ[(size_t)i * PQLD + c];
        float4 q = *(const float4*)&PQ[(size_t)j * PQLD + 352 + c];
        float s[4] = { lrelu(p.x + q.x), lrelu(p.y + q.y), lrelu(p.z + q.z), lrelu(p.w + q.w) };
#pragma unroll
        for (int u = 0; u < 4; u++) {
            __nv_bfloat16 h = __float2bfloat16(s[u]);
            sAh[r * F_LDA + c + u] = h;
            sAl[r * F_LDA + c + u] = __float2bfloat16(s[u] - __bfloat162float(h));
        }
    }
    __syncthreads();

    // phase 2: A[128x352] @ W2[352x256]
    wmma::fragment<wmma::accumulator, 16, 16, 16, float> acc[2][4];
#pragma unroll
    for (int i = 0; i < 2; i++)
#pragma unroll
        for (int j = 0; j < 4; j++) wmma::fill_fragment(acc[i][j], 0.f);

    for (int k0 = 0; k0 < 352; k0 += 32) {
        for (int v = tid; v < 1024; v += 512) {
            int r = v >> 5, c = (v & 31) * 8;
            *(uint4*)&sWh[r * F_LDW + c] = *(const uint4*)&W2h[(size_t)(k0 + r) * 256 + c];
            *(uint4*)&sWl[r * F_LDW + c] = *(const uint4*)&W2l[(size_t)(k0 + r) * 256 + c];
        }
        __syncthreads();
#pragma unroll
        for (int kk = 0; kk < 32; kk += 16) {
            wmma::fragment<wmma::matrix_a, 16, 16, 16, __nv_bfloat16, wmma::row_major> ah[2], al[2];
#pragma unroll
            for (int i = 0; i < 2; i++) {
                wmma::load_matrix_sync(ah[i], &sAh[(wm * 32 + i * 16) * F_LDA + k0 + kk], F_LDA);
                wmma::load_matrix_sync(al[i], &sAl[(wm * 32 + i * 16) * F_LDA + k0 + kk], F_LDA);
            }
#pragma unroll
            for (int j = 0; j < 4; j++) {
                wmma::fragment<wmma::matrix_b, 16, 16, 16, __nv_bfloat16, wmma::row_major> bh, bl;
                wmma::load_matrix_sync(bh, &sWh[kk * F_LDW + wn * 64 + j * 16], F_LDW);
                wmma::load_matrix_sync(bl, &sWl[kk * F_LDW + wn * 64 + j * 16], F_LDW);
#pragma unroll
                for (int i = 0; i < 2; i++) {
                    wmma::mma_sync(acc[i][j], ah[i], bh, acc[i][j]);
                    wmma::mma_sync(acc[i][j], al[i], bh, acc[i][j]);
                    wmma::mma_sync(acc[i][j], ah[i], bl, acc[i][j]);
                }
            }
        }
        __syncthreads();
    }

    // phase 3: store C to smem, then max over k + bias + lrelu
#pragma unroll
    for (int i = 0; i < 2; i++)
#pragma unroll
        for (int j = 0; j < 4; j++)
            wmma::store_matrix_sync(&sC[(wm * 32 + i * 16) * F_LDW + wn * 64 + j * 16], acc[i][j],
                                    F_LDW, wmma::mem_row_major);
    __syncthreads();

    for (int v = tid; v < 16 * 256; v += 512) {
        int ln = v >> 8, c = v & 255;
        float m = sC[(ln * 8) * F_LDW + c];
#pragma unroll
        for (int k = 1; k < KNB; k++) m = fmaxf(m, sC[(ln * 8 + k) * F_LDW + c]);
        CAT[(size_t)(node0 + ln) * CATD + colOff + c] = lrelu(m + b2[c]);
    }
}

// ---------------- misc ----------------
__global__ void de_copyx(const float* __restrict__ x, float* __restrict__ CAT) {
    int i = blockIdx.x * blockDim.x + threadIdx.x;
    if (i >= NODES * 6) return;
    int node = i / 6, f = i % 6;
    CAT[(size_t)node * CATD + f] = x[(size_t)node * 6 + f];
}

__global__ void de_mean(const float* __restrict__ H, float* __restrict__ G) {
    int b = blockIdx.x, c = threadIdx.x;
    float s = 0.f;
    for (int n = 0; n < NN; n++) s += H[((size_t)b * NN + n) * 256 + c];
    G[b * 256 + c] = s * (1.f / NN);
}

__global__ void de_head1(const float* __restrict__ G, const float* __restrict__ W,
                         const float* __restrict__ bias, float* __restrict__ T) {
    int b = blockIdx.x, j = threadIdx.x;
    float s = bias[j];
    for (int c = 0; c < 256; c++) s += G[b * 256 + c] * W[c * 128 + j];
    T[b * 128 + j] = lrelu(s);
}

__global__ void de_head2(const float* __restrict__ T, const float* __restrict__ W,
                         const float* __restrict__ bias, float* __restrict__ out) {
    int b = blockIdx.x, o = threadIdx.x;
    if (o >= 3) return;
    float s = bias[o];
    for (int j = 0; j < 128; j++) s += T[b * 128 + j] * W[j * 3 + o];
    out[b * 3 + o] = s;
}

// ---------------- launch ----------------
extern "C" void kernel_launch(void* const* d_in, const int* in_sizes, int n_in,
                              void* d_out, int out_size) {
    (void)in_sizes; (void)n_in; (void)out_size;
    const float* x = (const float*)d_in[0];
    const float* cw1[4], *cb1[4], *cw2[4], *cb2[4];
    for (int l = 0; l < 4; l++) {
        cw1[l] = (const float*)d_in[3 + 4 * l];
        cb1[l] = (const float*)d_in[4 + 4 * l];
        cw2[l] = (const float*)d_in[5 + 4 * l];
        cb2[l] = (const float*)d_in[6 + 4 * l];
    }
    const float* m1w1 = (const float*)d_in[19];
    const float* m1b1 = (const float*)d_in[20];
    const float* m1w2 = (const float*)d_in[21];
    const float* m1b2 = (const float*)d_in[22];
    const float* m2w1 = (const float*)d_in[23];
    const float* m2b1 = (const float*)d_in[24];
    const float* m2w2 = (const float*)d_in[25];
    const float* m2b2 = (const float*)d_in[26];

    float *D, *PQ, *CAT, *X2, *G, *T, *H2, *BC;
    __nv_bfloat16 *Xh, *Xl, *CATh, *CATl, *H1h, *H1l;
    __nv_bfloat16 *Wch, *Wcl, *W2ph, *W2pl, *W1h, *W1l;
    int* IDX;
    cudaGetSymbolAddress((void**)&D,    g_D);
    cudaGetSymbolAddress((void**)&PQ,   g_PQ);
    cudaGetSymbolAddress((void**)&Xh,   g_Xh);
    cudaGetSymbolAddress((void**)&Xl,   g_Xl);
    cudaGetSymbolAddress((void**)&CAT,  g_CAT);
    cudaGetSymbolAddress((void**)&CATh, g_CATh);
    cudaGetSymbolAddress((void**)&CATl, g_CATl);
    cudaGetSymbolAddress((void**)&H1h,  g_H1h);
    cudaGetSymbolAddress((void**)&H1l,  g_H1l);
    cudaGetSymbolAddress((void**)&H2,   g_H2);
    cudaGetSymbolAddress((void**)&X2,   g_X2);
    cudaGetSymbolAddress((void**)&IDX,  g_IDX);
    cudaGetSymbolAddress((void**)&G,    g_G);
    cudaGetSymbolAddress((void**)&T,    g_T);
    cudaGetSymbolAddress((void**)&Wch,  g_Wch);
    cudaGetSymbolAddress((void**)&Wcl,  g_Wcl);
    cudaGetSymbolAddress((void**)&BC,   g_bc);
    cudaGetSymbolAddress((void**)&W2ph, g_W2ph);
    cudaGetSymbolAddress((void**)&W2pl, g_W2pl);
    cudaGetSymbolAddress((void**)&W1h,  g_W1h);
    cudaGetSymbolAddress((void**)&W1l,  g_W1l);

    cudaFuncSetAttribute(de_fused2, cudaFuncAttributeMaxDynamicSharedMemorySize, F2_SMEM);

    de_copyx<<<(NODES * 6 + 255) / 256, 256>>>(x, CAT);

    for (int l = 0; l < 4; l++) {
        const float* Xsrc;
        int ldx, F, off, Kpad;
        if (l == 0) { Xsrc = x; ldx = 6; F = 6; off = 6; Kpad = 32; }
        else { Xsrc = CAT + (6 + (l - 1) * 256); ldx = CATD; F = 256; off = 6 + l * 256; Kpad = 256; }

        de_sqnorm<<<(NODES + 255) / 256, 256>>>(Xsrc, ldx, F, X2);
        de_dist2<<<dim3(4, 4, NB), 256>>>(Xsrc, ldx, F, X2, D);
        de_topk2<<<NODES, 64>>>(D, IDX);

        // weight prep
        prep_wcomb<<<(F * PQLD + 255) / 256, 256>>>(cw1[l], cb1[l], F, Wch, Wcl, BC);
        prep_w2p<<<(352 * 256 + 255) / 256, 256>>>(cw2[l], W2ph, W2pl);

        // layer input -> bf16 hi/lo
        conv_pad<<<((size_t)NODES * Kpad + 255) / 256, 256>>>(Xsrc, ldx, F, Kpad, NODES, Xh, Xl);

        // PQ = X @ [Wd | Wb] + [b1 | 0]  (one GEMM, N=704)
        tc_gemm<2><<<dim3(PQLD / BN, NODES / BM), 256>>>(Xh, Xl, Wch, Wcl, BC,
                                                         PQ, nullptr, nullptr,
                                                         NODES, PQLD, F, Kpad, PQLD);

        // fused GEMM2 + max-agg -> CAT
        de_fused2<<<NODES / 16, 512, F2_SMEM>>>(PQ, IDX, W2ph, W2pl, cb2[l], CAT, off);
    }

    // mlp1: [NODES,1030] -> 336 -> 256
    conv_flat<<<(CATD * 336 + 255) / 256, 256>>>(m1w1, CATD * 336, W1h, W1l);
    prep_w2p<<<(352 * 256 + 255) / 256, 256>>>(m1w2, W2ph, W2pl);
    conv_pad<<<((size_t)NODES * CATP + 255) / 256, 256>>>(CAT, CATD, CATD, CATP, NODES, CATh, CATl);

    tc_gemm<1><<<dim3(6, NODES / BM), 256>>>(CATh, CATl, W1h, W1l, m1b1,
                                             nullptr, H1h, H1l, NODES, 336, CATD, CATP, H1P);
    tc_gemm<0><<<dim3(4, NODES / BM), 256>>>(H1h, H1l, W2ph, W2pl, m1b2,
                                             H2, nullptr, nullptr, NODES, 256, 336, H1P, 256);

    de_mean<<<NB, 256>>>(H2, G);
    de_head1<<<NB, 128>>>(G, m2w1, m2b1, T);
    de_head2<<<NB, 32>>>(T, m2w2, m2b2, (float*)d_out);
}

// round 9
// speedup vs baseline: 4.4461x; 1.0863x over previous
#include <cuda_runtime.h>
#include <cuda_bf16.h>
#include <mma.h>
#include <cstdint>

using namespace nvcuda;

#define NB 64
#define NN 512
#define KNB 8
#define NODES 32768
#define CATD 1030
#define CATP 1056
#define H1P  352
#define PQLD 704    // [P(336) pad16 | Q(336) pad16]

// ---------------- scratch ----------------
__device__ float g_D[(size_t)NODES * 512];
__device__ float g_PQ[(size_t)NODES * PQLD];
__device__ __nv_bfloat16 g_Xh[(size_t)NODES * 256];
__device__ __nv_bfloat16 g_Xl[(size_t)NODES * 256];
__device__ float g_CAT[(size_t)NODES * CATD];
__device__ __nv_bfloat16 g_CATh[(size_t)NODES * CATP];
__device__ __nv_bfloat16 g_CATl[(size_t)NODES * CATP];
__device__ __nv_bfloat16 g_H1h[(size_t)NODES * H1P];
__device__ __nv_bfloat16 g_H1l[(size_t)NODES * H1P];
__device__ float g_H2[(size_t)NODES * 256];
__device__ float g_X2[NODES];
__device__ int   g_IDX[NODES * KNB];
__device__ float g_G[64 * 256];
__device__ float g_T[64 * 128];
__device__ __nv_bfloat16 g_Wch[256 * PQLD];
__device__ __nv_bfloat16 g_Wcl[256 * PQLD];
__device__ float g_bc[PQLD];
__device__ __nv_bfloat16 g_W2ph[352 * 256];
__device__ __nv_bfloat16 g_W2pl[352 * 256];
__device__ __nv_bfloat16 g_W1h[1030 * 336];
__device__ __nv_bfloat16 g_W1l[1030 * 336];

__device__ __forceinline__ float lrelu(float v) { return (v >= 0.f) ? v : 0.01f * v; }

// ---------------- squared norms (fp32 source) ----------------
__global__ void de_sqnorm(const float* __restrict__ X, int ldx, int F, float* __restrict__ x2) {
    int i = blockIdx.x * blockDim.x + threadIdx.x;
    if (i < NODES) {
        const float* r = X + (size_t)i * ldx;
        float s = 0.f;
        for (int f = 0; f < F; f++) { float v = r[f]; s += v * v; }
        x2[i] = s;
    }
}

// ---------------- tensor-core pairwise distance ----------------
// D[n][m] = x2[n] + x2[m] - 2 * (X@X^T)[n][m], Gram via split-bf16 3-MMA.
#define DLDA 40
#define DIST_SMEM 67584   // max(4*10240 tile bytes, 128*132*4 epilogue)

__global__ __launch_bounds__(256)
void de_dist_tc(const __nv_bfloat16* __restrict__ Xh, const __nv_bfloat16* __restrict__ Xl,
                int Kpad, const float* __restrict__ x2, float* __restrict__ D)
{
    extern __shared__ __align__(16) char smem[];
    __nv_bfloat16* sAh = (__nv_bfloat16*)smem;              // 128 x 40
    __nv_bfloat16* sAl = (__nv_bfloat16*)(smem + 10240);
    __nv_bfloat16* sBh = (__nv_bfloat16*)(smem + 20480);
    __nv_bfloat16* sBl = (__nv_bfloat16*)(smem + 30720);
    float* sC = (float*)smem;                               // reuse, ld 132

    int b = blockIdx.z;
    int n0 = blockIdx.y * 128, m0 = blockIdx.x * 128;
    int nb = b * NN;
    int tid = threadIdx.x;
    int warp = tid >> 5;
    int wm = warp >> 1;   // 4 row slabs of 32
    int wn = warp & 1;    // 2 col slabs of 64

    wmma::fragment<wmma::accumulator, 16, 16, 16, float> acc[2][4];
#pragma unroll
    for (int i = 0; i < 2; i++)
#pragma unroll
        for (int j = 0; j < 4; j++) wmma::fill_fragment(acc[i][j], 0.f);

    for (int k0 = 0; k0 < Kpad; k0 += 32) {
        for (int v = tid; v < 512; v += 256) {
            int r = v >> 2, c = (v & 3) * 8;
            size_t gA = (size_t)(nb + n0 + r) * Kpad + k0 + c;
            size_t gB = (size_t)(nb + m0 + r) * Kpad + k0 + c;
            *(uint4*)&sAh[r * DLDA + c] = *(const uint4*)&Xh[gA];
            *(uint4*)&sAl[r * DLDA + c] = *(const uint4*)&Xl[gA];
            *(uint4*)&sBh[r * DLDA + c] = *(const uint4*)&Xh[gB];
            *(uint4*)&sBl[r * DLDA + c] = *(const uint4*)&Xl[gB];
        }
        __syncthreads();
#pragma unroll
        for (int kk = 0; kk < 32; kk += 16) {
            wmma::fragment<wmma::matrix_a, 16, 16, 16, __nv_bfloat16, wmma::row_major> ah[2], al[2];
#pragma unroll
            for (int i = 0; i < 2; i++) {
                wmma::load_matrix_sync(ah[i], &sAh[(wm * 32 + i * 16) * DLDA + kk], DLDA);
                wmma::load_matrix_sync(al[i], &sAl[(wm * 32 + i * 16) * DLDA + kk], DLDA);
            }
#pragma unroll
            for (int j = 0; j < 4; j++) {
                wmma::fragment<wmma::matrix_b, 16, 16, 16, __nv_bfloat16, wmma::col_major> bh, bl;
                wmma::load_matrix_sync(bh, &sBh[(wn * 64 + j * 16) * DLDA + kk], DLDA);
                wmma::load_matrix_sync(bl, &sBl[(wn * 64 + j * 16) * DLDA + kk], DLDA);
#pragma unroll
                for (int i = 0; i < 2; i++) {
                    wmma::mma_sync(acc[i][j], ah[i], bh, acc[i][j]);
                    wmma::mma_sync(acc[i][j], al[i], bh, acc[i][j]);
                    wmma::mma_sync(acc[i][j], ah[i], bl, acc[i][j]);
                }
            }
        }
        __syncthreads();
    }

#pragma unroll
    for (int i = 0; i < 2; i++)
#pragma unroll
        for (int j = 0; j < 4; j++)
            wmma::store_matrix_sync(&sC[(wm * 32 + i * 16) * 132 + wn * 64 + j * 16], acc[i][j],
                                    132, wmma::mem_row_major);
    __syncthreads();

    for (int v = tid; v < 128 * 128; v += 256) {
        int r = v >> 7, c = v & 127;
        D[(size_t)(nb + n0 + r) * NN + m0 + c] =
            x2[nb + n0 + r] + x2[nb + m0 + c] - 2.f * sC[r * 132 + c];
    }
}

// ---------------- top-8 smallest (64 threads, registers + shuffle) ----------------
__global__ void de_topk2(const float* __restrict__ D, int* __restrict__ out) {
    int row = blockIdx.x;
    int tid = threadIdx.x;
    const float* d = D + (size_t)row * NN;
    float v[8];
#pragma unroll
    for (int j = 0; j < 8; j++) v[j] = d[tid + 64 * j];
    __shared__ float sv[2];
    __shared__ int   si[2];
    __shared__ int   schosen;
    for (int t = 0; t < KNB; t++) {
        float bv = v[0]; int bj = 0;
#pragma unroll
        for (int j = 1; j < 8; j++) if (v[j] < bv) { bv = v[j]; bj = j; }
        int bidx = tid + 64 * bj;
#pragma unroll
        for (int s = 16; s > 0; s >>= 1) {
            float ov = __shfl_down_sync(0xFFFFFFFFu, bv, s);
            int   oi = __shfl_down_sync(0xFFFFFFFFu, bidx, s);
            if (ov < bv || (ov == bv && oi < bidx)) { bv = ov; bidx = oi; }
        }
        if ((tid & 31) == 0) { sv[tid >> 5] = bv; si[tid >> 5] = bidx; }
        __syncthreads();
        if (tid == 0) {
            int w = (sv[1] < sv[0] || (sv[1] == sv[0] && si[1] < si[0])) ? 1 : 0;
            schosen = si[w];
            out[row * KNB + t] = si[w];
        }
        __syncthreads();
        int ch = schosen;
        if ((ch & 63) == tid) v[ch >> 6] = 3.4e38f;
        __syncthreads();
    }
}

// ---------------- fp32 -> bf16 hi/lo helpers ----------------
__global__ void conv_flat(const float* __restrict__ X, int n,
                          __nv_bfloat16* __restrict__ H, __nv_bfloat16* __restrict__ L) {
    int i = blockIdx.x * blockDim.x + threadIdx.x;
    if (i >= n) return;
    float v = X[i];
    __nv_bfloat16 h = __float2bfloat16(v);
    H[i] = h;
    L[i] = __float2bfloat16(v - __bfloat162float(h));
}

__global__ void conv_pad(const float* __restrict__ X, int ldx, int Kvalid, int Kpad, int M,
                         __nv_bfloat16* __restrict__ H, __nv_bfloat16* __restrict__ L) {
    int i = blockIdx.x * blockDim.x + threadIdx.x;
    if (i >= M * Kpad) return;
    int r = i / Kpad, c = i - r * Kpad;
    float v = (c < Kvalid) ? X[(size_t)r * ldx + c] : 0.f;
    __nv_bfloat16 h = __float2bfloat16(v);
    H[i] = h;
    L[i] = __float2bfloat16(v - __bfloat162float(h));
}

// ---------------- combined weight prep: [F, 704] = [Wtop-Wbot | 0 | Wbot | 0] ----------------
__global__ void prep_wcomb(const float* __restrict__ w1, const float* __restrict__ b1, int F,
                           __nv_bfloat16* __restrict__ Wh, __nv_bfloat16* __restrict__ Wl,
                           float* __restrict__ bc) {
    int i = blockIdx.x * blockDim.x + threadIdx.x;
    if (i >= F * PQLD) return;
    int k = i / PQLD, c = i - k * PQLD;
    float v = 0.f;
    if (c < 336) v = w1[k * 336 + c] - w1[(F + k) * 336 + c];
    else if (c >= 352 && c < 688) v = w1[(size_t)(F + k) * 336 + (c - 352)];
    __nv_bfloat16 h = __float2bfloat16(v);
    Wh[i] = h;
    Wl[i] = __float2bfloat16(v - __bfloat162float(h));
    if (k == 0) bc[c] = (c < 336) ? b1[c] : 0.f;
}

// ---------------- W2 padded to [352][256] hi/lo ----------------
__global__ void prep_w2p(const float* __restrict__ w2,
                         __nv_bfloat16* __restrict__ H, __nv_bfloat16* __restrict__ L) {
    int i = blockIdx.x * blockDim.x + threadIdx.x;
    if (i >= 352 * 256) return;
    int k = i >> 8;
    float v = (k < 336) ? w2[i] : 0.f;
    __nv_bfloat16 h = __float2bfloat16(v);
    H[i] = h;
    L[i] = __float2bfloat16(v - __bfloat162float(h));
}

// ---------------- tensor-core GEMM (split-bf16, 3 MMA) ----------------
#define BM 128
#define BN 64
#define BK 32

template<int OUTMODE>
__global__ __launch_bounds__(256)
void tc_gemm(const __nv_bfloat16* __restrict__ Ah, const __nv_bfloat16* __restrict__ Al,
             const __nv_bfloat16* __restrict__ Wh, const __nv_bfloat16* __restrict__ Wl,
             const float* __restrict__ bias,
             float* __restrict__ Cf, __nv_bfloat16* __restrict__ Ch, __nv_bfloat16* __restrict__ Cl,
             int M, int N, int K, int Kpad, int ldout)
{
    __shared__ __align__(16) char smem[35840];
    __nv_bfloat16 (*sAh)[BK + 8] = (__nv_bfloat16(*)[BK + 8])(smem);
    __nv_bfloat16 (*sAl)[BK + 8] = (__nv_bfloat16(*)[BK + 8])(smem + 10240);
    __nv_bfloat16 (*sWh)[BN + 8] = (__nv_bfloat16(*)[BN + 8])(smem + 20480);
    __nv_bfloat16 (*sWl)[BN + 8] = (__nv_bfloat16(*)[BN + 8])(smem + 25088);
    float (*sC)[BN + 4] = (float(*)[BN + 4])(smem);

    int m0 = blockIdx.y * BM;
    int n0 = blockIdx.x * BN;
    int tid = threadIdx.x;
    int warp = tid >> 5;
    int wm = warp >> 1;
    int wn = warp & 1;

    wmma::fragment<wmma::accumulator, 16, 16, 16, float> acc[2][2];
#pragma unroll
    for (int i = 0; i < 2; i++)
#pragma unroll
        for (int j = 0; j < 2; j++) wmma::fill_fragment(acc[i][j], 0.f);

    for (int k0 = 0; k0 < Kpad; k0 += BK) {
        for (int v = tid; v < BM * BK / 8; v += 256) {
            int r = v >> 2;
            int c = (v & 3) * 8;
            size_t gi = (size_t)(m0 + r) * Kpad + k0 + c;
            *(uint4*)&sAh[r][c] = *(const uint4*)&Ah[gi];
            *(uint4*)&sAl[r][c] = *(const uint4*)&Al[gi];
        }
        for (int v = tid; v < BK * BN; v += 256) {
            int r = v >> 6, c = v & 63;
            int k = k0 + r, n = n0 + c;
            bool in = (k < K) && (n < N);
            sWh[r][c] = in ? Wh[(size_t)k * N + n] : __float2bfloat16(0.f);
            sWl[r][c] = in ? Wl[(size_t)k * N + n] : __float2bfloat16(0.f);
        }
        __syncthreads();
#pragma unroll
        for (int kk = 0; kk < BK; kk += 16) {
            wmma::fragment<wmma::matrix_a, 16, 16, 16, __nv_bfloat16, wmma::row_major> ah[2], al[2];
            wmma::fragment<wmma::matrix_b, 16, 16, 16, __nv_bfloat16, wmma::row_major> bh[2], bl[2];
#pragma unroll
            for (int i = 0; i < 2; i++) {
                wmma::load_matrix_sync(ah[i], &sAh[wm * 32 + i * 16][kk], BK + 8);
                wmma::load_matrix_sync(al[i], &sAl[wm * 32 + i * 16][kk], BK + 8);
            }
#pragma unroll
            for (int j = 0; j < 2; j++) {
                wmma::load_matrix_sync(bh[j], &sWh[kk][wn * 32 + j * 16], BN + 8);
                wmma::load_matrix_sync(bl[j], &sWl[kk][wn * 32 + j * 16], BN + 8);
            }
#pragma unroll
            for (int i = 0; i < 2; i++)
#pragma unroll
                for (int j = 0; j < 2; j++) {
                    wmma::mma_sync(acc[i][j], ah[i], bh[j], acc[i][j]);
                    wmma::mma_sync(acc[i][j], al[i], bh[j], acc[i][j]);
                    wmma::mma_sync(acc[i][j], ah[i], bl[j], acc[i][j]);
                }
        }
        __syncthreads();
    }

#pragma unroll
    for (int i = 0; i < 2; i++)
#pragma unroll
        for (int j = 0; j < 2; j++)
            wmma::store_matrix_sync(&sC[wm * 32 + i * 16][wn * 32 + j * 16], acc[i][j],
                                    BN + 4, wmma::mem_row_major);
    __syncthreads();

    for (int v = tid; v < BM * BN; v += 256) {
        int r = v >> 6, c = v & 63;
        int m = m0 + r, n = n0 + c;
        if (m >= M) continue;
        if (OUTMODE == 0) {
            if (n < N) Cf[(size_t)m * ldout + n] = lrelu(sC[r][c] + bias[n]);
        } else if (OUTMODE == 1) {
            if (n < ldout) {
                float val = (n < N) ? lrelu(sC[r][c] + bias[n]) : 0.f;
                __nv_bfloat16 h = __float2bfloat16(val);
                Ch[(size_t)m * ldout + n] = h;
                Cl[(size_t)m * ldout + n] = __float2bfloat16(val - __bfloat162float(h));
            }
        } else {
            if (n < ldout) {
                float val = (n < N) ? (sC[r][c] + bias[n]) : 0.f;
                Cf[(size_t)m * ldout + n] = val;
            }
        }
    }
}

// ---------------- fused GEMM2 + bias + lrelu + max-agg (16 nodes / 128 edge rows) ----------------
#define F_LDA 368
#define F_LDW 264
#define F2_SMEM (94208 * 2 + 16896 * 2)

__global__ __launch_bounds__(512)
void de_fused2(const float* __restrict__ PQ,
               const int* __restrict__ idx,
               const __nv_bfloat16* __restrict__ W2h, const __nv_bfloat16* __restrict__ W2l,
               const float* __restrict__ b2, float* __restrict__ CAT, int colOff)
{
    extern __shared__ __align__(16) char smem[];
    __nv_bfloat16* sAh = (__nv_bfloat16*)smem;                   // 128 x 368
    __nv_bfloat16* sAl = sAh + 128 * F_LDA;
    __nv_bfloat16* sWh = (__nv_bfloat16*)(smem + 94208 * 2);     // 32 x 264
    __nv_bfloat16* sWl = sWh + 32 * F_LDW;
    float* sC = (float*)smem;                                    // reuse, ld 264

    int node0 = blockIdx.x * 16;
    int gbase = (node0 >> 9) << 9;
    int tid = threadIdx.x;
    int warp = tid >> 5;
    int wm = warp & 3;
    int wn = warp >> 2;

    for (int v = tid; v < 128 * 88; v += 512) {
        int r = v / 88, c = (v - r * 88) * 4;
        int i = node0 + (r >> 3);
        int j = gbase + idx[i * KNB + (r & 7)];
        float4 p = *(const float4*)&PQ[(size_t)i * PQLD + c];
        float4 q = *(const float4*)&PQ[(size_t)j * PQLD + 352 + c];
        float s[4] = { lrelu(p.x + q.x), lrelu(p.y + q.y), lrelu(p.z + q.z), lrelu(p.w + q.w) };
#pragma unroll
        for (int u = 0; u < 4; u++) {
            __nv_bfloat16 h = __float2bfloat16(s[u]);
            sAh[r * F_LDA + c + u] = h;
            sAl[r * F_LDA + c + u] = __float2bfloat16(s[u] - __bfloat162float(h));
        }
    }
    __syncthreads();

    wmma::fragment<wmma::accumulator, 16, 16, 16, float> acc[2][4];
#pragma unroll
    for (int i = 0; i < 2; i++)
#pragma unroll
        for (int j = 0; j < 4; j++) wmma::fill_fragment(acc[i][j], 0.f);

    for (int k0 = 0; k0 < 352; k0 += 32) {
        for (int v = tid; v < 1024; v += 512) {
            int r = v >> 5, c = (v & 31) * 8;
            *(uint4*)&sWh[r * F_LDW + c] = *(const uint4*)&W2h[(size_t)(k0 + r) * 256 + c];
            *(uint4*)&sWl[r * F_LDW + c] = *(const uint4*)&W2l[(size_t)(k0 + r) * 256 + c];
        }
        __syncthreads();
#pragma unroll
        for (int kk = 0; kk < 32; kk += 16) {
            wmma::fragment<wmma::matrix_a, 16, 16, 16, __nv_bfloat16, wmma::row_major> ah[2], al[2];
#pragma unroll
            for (int i = 0; i < 2; i++) {
                wmma::load_matrix_sync(ah[i], &sAh[(wm * 32 + i * 16) * F_LDA + k0 + kk], F_LDA);
                wmma::load_matrix_sync(al[i], &sAl[(wm * 32 + i * 16) * F_LDA + k0 + kk], F_LDA);
            }
#pragma unroll
            for (int j = 0; j < 4; j++) {
                wmma::fragment<wmma::matrix_b, 16, 16, 16, __nv_bfloat16, wmma::row_major> bh, bl;
                wmma::load_matrix_sync(bh, &sWh[kk * F_LDW + wn * 64 + j * 16], F_LDW);
                wmma::load_matrix_sync(bl, &sWl[kk * F_LDW + wn * 64 + j * 16], F_LDW);
#pragma unroll
                for (int i = 0; i < 2; i++) {
                    wmma::mma_sync(acc[i][j], ah[i], bh, acc[i][j]);
                    wmma::mma_sync(acc[i][j], al[i], bh, acc[i][j]);
                    wmma::mma_sync(acc[i][j], ah[i], bl, acc[i][j]);
                }
            }
        }
        __syncthreads();
    }

#pragma unroll
    for (int i = 0; i < 2; i++)
#pragma unroll
        for (int j = 0; j < 4; j++)
            wmma::store_matrix_sync(&sC[(wm * 32 + i * 16) * F_LDW + wn * 64 + j * 16], acc[i][j],
                                    F_LDW, wmma::mem_row_major);
    __syncthreads();

    for (int v = tid; v < 16 * 256; v += 512) {
        int ln = v >> 8, c = v & 255;
        float m = sC[(ln * 8) * F_LDW + c];
#pragma unroll
        for (int k = 1; k < KNB; k++) m = fmaxf(m, sC[(ln * 8 + k) * F_LDW + c]);
        CAT[(size_t)(node0 + ln) * CATD + colOff + c] = lrelu(m + b2[c]);
    }
}

// ---------------- misc ----------------
__global__ void de_copyx(const float* __restrict__ x, float* __restrict__ CAT) {
    int i = blockIdx.x * blockDim.x + threadIdx.x;
    if (i >= NODES * 6) return;
    int node = i / 6, f = i % 6;
    CAT[(size_t)node * CATD + f] = x[(size_t)node * 6 + f];
}

__global__ void de_mean(const float* __restrict__ H, float* __restrict__ G) {
    int b = blockIdx.x, c = threadIdx.x;
    float s = 0.f;
    for (int n = 0; n < NN; n++) s += H[((size_t)b * NN + n) * 256 + c];
    G[b * 256 + c] = s * (1.f / NN);
}

__global__ void de_head1(const float* __restrict__ G, const float* __restrict__ W,
                         const float* __restrict__ bias, float* __restrict__ T) {
    int b = blockIdx.x, j = threadIdx.x;
    float s = bias[j];
    for (int c = 0; c < 256; c++) s += G[b * 256 + c] * W[c * 128 + j];
    T[b * 128 + j] = lrelu(s);
}

__global__ void de_head2(const float* __restrict__ T, const float* __restrict__ W,
                         const float* __restrict__ bias, float* __restrict__ out) {
    int b = blockIdx.x, o = threadIdx.x;
    if (o >= 3) return;
    float s = bias[o];
    for (int j = 0; j < 128; j++) s += T[b * 128 + j] * W[j * 3 + o];
    out[b * 3 + o] = s;
}

// ---------------- launch ----------------
extern "C" void kernel_launch(void* const* d_in, const int* in_sizes, int n_in,
                              void* d_out, int out_size) {
    (void)in_sizes; (void)n_in; (void)out_size;
    const float* x = (const float*)d_in[0];
    const float* cw1[4], *cb1[4], *cw2[4], *cb2[4];
    for (int l = 0; l < 4; l++) {
        cw1[l] = (const float*)d_in[3 + 4 * l];
        cb1[l] = (const float*)d_in[4 + 4 * l];
        cw2[l] = (const float*)d_in[5 + 4 * l];
        cb2[l] = (const float*)d_in[6 + 4 * l];
    }
    const float* m1w1 = (const float*)d_in[19];
    const float* m1b1 = (const float*)d_in[20];
    const float* m1w2 = (const float*)d_in[21];
    const float* m1b2 = (const float*)d_in[22];
    const float* m2w1 = (const float*)d_in[23];
    const float* m2b1 = (const float*)d_in[24];
    const float* m2w2 = (const float*)d_in[25];
    const float* m2b2 = (const float*)d_in[26];

    float *D, *PQ, *CAT, *X2, *G, *T, *H2, *BC;
    __nv_bfloat16 *Xh, *Xl, *CATh, *CATl, *H1h, *H1l;
    __nv_bfloat16 *Wch, *Wcl, *W2ph, *W2pl, *W1h, *W1l;
    int* IDX;
    cudaGetSymbolAddress((void**)&D,    g_D);
    cudaGetSymbolAddress((void**)&PQ,   g_PQ);
    cudaGetSymbolAddress((void**)&Xh,   g_Xh);
    cudaGetSymbolAddress((void**)&Xl,   g_Xl);
    cudaGetSymbolAddress((void**)&CAT,  g_CAT);
    cudaGetSymbolAddress((void**)&CATh, g_CATh);
    cudaGetSymbolAddress((void**)&CATl, g_CATl);
    cudaGetSymbolAddress((void**)&H1h,  g_H1h);
    cudaGetSymbolAddress((void**)&H1l,  g_H1l);
    cudaGetSymbolAddress((void**)&H2,   g_H2);
    cudaGetSymbolAddress((void**)&X2,   g_X2);
    cudaGetSymbolAddress((void**)&IDX,  g_IDX);
    cudaGetSymbolAddress((void**)&G,    g_G);
    cudaGetSymbolAddress((void**)&T,    g_T);
    cudaGetSymbolAddress((void**)&Wch,  g_Wch);
    cudaGetSymbolAddress((void**)&Wcl,  g_Wcl);
    cudaGetSymbolAddress((void**)&BC,   g_bc);
    cudaGetSymbolAddress((void**)&W2ph, g_W2ph);
    cudaGetSymbolAddress((void**)&W2pl, g_W2pl);
    cudaGetSymbolAddress((void**)&W1h,  g_W1h);
    cudaGetSymbolAddress((void**)&W1l,  g_W1l);

    cudaFuncSetAttribute(de_fused2, cudaFuncAttributeMaxDynamicSharedMemorySize, F2_SMEM);
    cudaFuncSetAttribute(de_dist_tc, cudaFuncAttributeMaxDynamicSharedMemorySize, DIST_SMEM);

    de_copyx<<<(NODES * 6 + 255) / 256, 256>>>(x, CAT);

    for (int l = 0; l < 4; l++) {
        const float* Xsrc;
        int ldx, F, off, Kpad;
        if (l == 0) { Xsrc = x; ldx = 6; F = 6; off = 6; Kpad = 32; }
        else { Xsrc = CAT + (6 + (l - 1) * 256); ldx = CATD; F = 256; off = 6 + l * 256; Kpad = 256; }

        // layer input -> bf16 hi/lo FIRST (consumed by dist + PQ gemm)
        conv_pad<<<((size_t)NODES * Kpad + 255) / 256, 256>>>(Xsrc, ldx, F, Kpad, NODES, Xh, Xl);
        de_sqnorm<<<(NODES + 255) / 256, 256>>>(Xsrc, ldx, F, X2);

        // tensor-core pairwise distances
        de_dist_tc<<<dim3(4, 4, NB), 256, DIST_SMEM>>>(Xh, Xl, Kpad, X2, D);
        de_topk2<<<NODES, 64>>>(D, IDX);

        // weight prep
        prep_wcomb<<<(F * PQLD + 255) / 256, 256>>>(cw1[l], cb1[l], F, Wch, Wcl, BC);
        prep_w2p<<<(352 * 256 + 255) / 256, 256>>>(cw2[l], W2ph, W2pl);

        // PQ = X @ [Wd | Wb] + [b1 | 0]  (one GEMM, N=704)
        tc_gemm<2><<<dim3(PQLD / BN, NODES / BM), 256>>>(Xh, Xl, Wch, Wcl, BC,
                                                         PQ, nullptr, nullptr,
                                                         NODES, PQLD, F, Kpad, PQLD);

        // fused GEMM2 + max-agg -> CAT
        de_fused2<<<NODES / 16, 512, F2_SMEM>>>(PQ, IDX, W2ph, W2pl, cb2[l], CAT, off);
    }

    // mlp1: [NODES,1030] -> 336 -> 256
    conv_flat<<<(CATD * 336 + 255) / 256, 256>>>(m1w1, CATD * 336, W1h, W1l);
    prep_w2p<<<(352 * 256 + 255) / 256, 256>>>(m1w2, W2ph, W2pl);
    conv_pad<<<((size_t)NODES * CATP + 255) / 256, 256>>>(CAT, CATD, CATD, CATP, NODES, CATh, CATl);

    tc_gemm<1><<<dim3(6, NODES / BM), 256>>>(CATh, CATl, W1h, W1l, m1b1,
                                             nullptr, H1h, H1l, NODES, 336, CATD, CATP, H1P);
    tc_gemm<0><<<dim3(4, NODES / BM), 256>>>(H1h, H1l, W2ph, W2pl, m1b2,
                                             H2, nullptr, nullptr, NODES, 256, 336, H1P, 256);

    de_mean<<<NB, 256>>>(H2, G);
    de_head1<<<NB, 128>>>(G, m2w1, m2b1, T);
    de_head2<<<NB, 32>>>(T, m2w2, m2b2, (float*)d_out);
}